// round 1
// baseline (speedup 1.0000x reference)
#include <cuda_runtime.h>
#include <cstdint>
#include <cstddef>

// Problem constants
#define Bq   2
#define Nt   8192
#define Dd   1024
#define Hh   16
#define DH   64
#define Mrows (Bq * Nt)          // 16384
#define NSPLIT 16                // Gram token splits

// ---------------- scratch (static device allocations, no cudaMalloc) -------
__device__ float g_qk[(size_t)Mrows * Dd];              // 64 MB
__device__ float g_v [(size_t)Mrows * Dd];              // 64 MB
__device__ float g_gpart[(size_t)Bq * Hh * NSPLIT * DH * DH]; // 8 MB
__device__ float g_attn [(size_t)Bq * Hh * DH * DH];    // 0.5 MB
__device__ float g_m    [(size_t)Bq * Dd * Dd];         // 8 MB

// ---------------- generic 128x128x16 fp32 GEMM tile (N=K=1024 fixed) -------
// A: row-major (rows x 1024), B: row-major (1024 x 1024), C: row-major (rows x 1024)
__device__ __forceinline__ void sgemm1024(const float* __restrict__ A,
                                          const float* __restrict__ B,
                                          float* __restrict__ C,
                                          int bm, int bn)
{
    __shared__ float As[16][128];
    __shared__ float Bs[16][128];

    const int tid = threadIdx.x;          // 256 threads
    const int tx  = tid & 15;             // 16 col groups
    const int ty  = tid >> 4;             // 16 row groups

    float acc[8][8];
    #pragma unroll
    for (int i = 0; i < 8; i++)
        #pragma unroll
        for (int j = 0; j < 8; j++) acc[i][j] = 0.0f;

    const int a_row  = tid >> 2;          // 0..63
    const int a_col4 = (tid & 3) * 4;     // 0,4,8,12
    const int b_row  = tid >> 5;          // 0..7
    const int b_col4 = (tid & 31) * 4;    // 0..124

    const float* Ab = A + (size_t)bm * 1024;
    const float* Bb = B + bn;

    for (int k0 = 0; k0 < 1024; k0 += 16) {
        #pragma unroll
        for (int i = 0; i < 2; i++) {
            int r = a_row + i * 64;
            float4 v = *(const float4*)(Ab + (size_t)r * 1024 + k0 + a_col4);
            As[a_col4 + 0][r] = v.x;
            As[a_col4 + 1][r] = v.y;
            As[a_col4 + 2][r] = v.z;
            As[a_col4 + 3][r] = v.w;
        }
        #pragma unroll
        for (int i = 0; i < 2; i++) {
            int r = b_row + i * 8;
            *(float4*)&Bs[r][b_col4] =
                *(const float4*)(Bb + (size_t)(k0 + r) * 1024 + b_col4);
        }
        __syncthreads();

        #pragma unroll
        for (int kk = 0; kk < 16; kk++) {
            float ra[8], rb[8];
            *(float4*)&ra[0] = *(float4*)&As[kk][ty * 8];
            *(float4*)&ra[4] = *(float4*)&As[kk][ty * 8 + 4];
            *(float4*)&rb[0] = *(float4*)&Bs[kk][tx * 8];
            *(float4*)&rb[4] = *(float4*)&Bs[kk][tx * 8 + 4];
            #pragma unroll
            for (int i = 0; i < 8; i++)
                #pragma unroll
                for (int j = 0; j < 8; j++)
                    acc[i][j] += ra[i] * rb[j];
        }
        __syncthreads();
    }

    #pragma unroll
    for (int i = 0; i < 8; i++) {
        float* cp = C + (size_t)(bm + ty * 8 + i) * 1024 + bn + tx * 8;
        *(float4*)(cp)     = make_float4(acc[i][0], acc[i][1], acc[i][2], acc[i][3]);
        *(float4*)(cp + 4) = make_float4(acc[i][4], acc[i][5], acc[i][6], acc[i][7]);
    }
}

// K1: QK = X @ W_qk ; V = X @ W_v  (z selects which)
__global__ __launch_bounds__(256, 2)
void proj_kernel(const float* __restrict__ x,
                 const float* __restrict__ Wqk,
                 const float* __restrict__ Wv,
                 float* __restrict__ QK, float* __restrict__ V)
{
    const float* Bm = blockIdx.z ? Wv : Wqk;
    float*       Cm = blockIdx.z ? V  : QK;
    sgemm1024(x, Bm, Cm, blockIdx.y * 128, blockIdx.x * 128);
}

// K3: partial Gram per (b,h): G[c,d] = sum_n QK[b,n,h*64+c]*QK[b,n,h*64+d]
// grid (32, NSPLIT), 256 threads; each block covers 512 tokens.
__global__ __launch_bounds__(256)
void gram_partial(const float* __restrict__ QK, float* __restrict__ Gpart)
{
    const int bh = blockIdx.x;           // 0..31
    const int sp = blockIdx.y;           // 0..15
    const int b  = bh >> 4;
    const int h  = bh & 15;
    const float* A = QK + (size_t)b * Nt * Dd + h * DH;  // row stride Dd

    __shared__ float As[32][64];
    const int tid = threadIdx.x;
    const int tx = tid & 15, ty = tid >> 4;

    float acc[4][4];
    #pragma unroll
    for (int i = 0; i < 4; i++)
        #pragma unroll
        for (int j = 0; j < 4; j++) acc[i][j] = 0.0f;

    const int n0base = sp * (Nt / NSPLIT);
    for (int n0 = n0base; n0 < n0base + Nt / NSPLIT; n0 += 32) {
        #pragma unroll
        for (int i = 0; i < 2; i++) {
            int idx = tid + i * 256;
            int r  = idx >> 4;
            int c4 = (idx & 15) * 4;
            *(float4*)&As[r][c4] = *(const float4*)(A + (size_t)(n0 + r) * Dd + c4);
        }
        __syncthreads();
        #pragma unroll
        for (int kk = 0; kk < 32; kk++) {
            float rc[4], rd[4];
            #pragma unroll
            for (int i = 0; i < 4; i++) rc[i] = As[kk][ty * 4 + i];
            #pragma unroll
            for (int j = 0; j < 4; j++) rd[j] = As[kk][tx * 4 + j];
            #pragma unroll
            for (int i = 0; i < 4; i++)
                #pragma unroll
                for (int j = 0; j < 4; j++)
                    acc[i][j] += rc[i] * rd[j];
        }
        __syncthreads();
    }

    float* gp = Gpart + ((size_t)bh * NSPLIT + sp) * (DH * DH);
    #pragma unroll
    for (int i = 0; i < 4; i++)
        #pragma unroll
        for (int j = 0; j < 4; j++)
            gp[(ty * 4 + i) * DH + tx * 4 + j] = acc[i][j];
}

// K4a: reduce partials + distance logits + softmax per row -> attn (c x d)
__global__ __launch_bounds__(256)
void softmax_kernel(const float* __restrict__ Gpart,
                    const float* __restrict__ tau,
                    float* __restrict__ attn)
{
    const int bh = blockIdx.x;
    const int h  = bh & 15;
    __shared__ float G[DH * DH];
    const int tid = threadIdx.x;

    const float* base = Gpart + (size_t)bh * NSPLIT * (DH * DH);
    for (int e = tid; e < DH * DH; e += 256) {
        float s = 0.0f;
        #pragma unroll
        for (int p = 0; p < NSPLIT; p++) s += base[(size_t)p * (DH * DH) + e];
        G[e] = s;
    }
    __syncthreads();

    if (tid < DH) {
        const int c = tid;
        const float tauh  = tau[h];
        const float scale = 0.011048543456039806f;  // 1/sqrt(8192)
        const float qc = G[c * DH + c];
        float l[DH];
        float mx = -1e30f;
        #pragma unroll 8
        for (int d = 0; d < DH; d++) {
            float v = (2.0f * G[c * DH + d] - qc - G[d * DH + d]) * scale * tauh;
            l[d] = v;
            mx = fmaxf(mx, v);
        }
        float sum = 0.0f;
        #pragma unroll 8
        for (int d = 0; d < DH; d++) { float e = __expf(l[d] - mx); l[d] = e; sum += e; }
        const float inv = 1.0f / sum;
        float* ap = attn + (size_t)bh * (DH * DH) + c * DH;
        #pragma unroll 8
        for (int d = 0; d < DH; d++) ap[d] = l[d] * inv;
    }
}

// K4b: M_b[h*64+d, j] = sum_c attn[bh][c,d] * W_out[h*64+c, j]
// grid (8 j-tiles, 32 bh), 256 threads
__global__ __launch_bounds__(256)
void build_m(const float* __restrict__ attn,
             const float* __restrict__ Wout,
             float* __restrict__ M)
{
    const int bh = blockIdx.y;
    const int b = bh >> 4, h = bh & 15;
    const int j0 = blockIdx.x * 128;

    __shared__ float Asm[DH * DH];     // attn[c][d]
    __shared__ float Ws[DH][128];      // W_out rows h*64.., col tile

    const int tid = threadIdx.x;
    const float* ap = attn + (size_t)bh * (DH * DH);
    for (int e = tid; e < DH * DH; e += 256) Asm[e] = ap[e];

    #pragma unroll
    for (int i = 0; i < 8; i++) {
        int idx = tid + i * 256;
        int r  = idx >> 5;
        int c4 = (idx & 31) * 4;
        *(float4*)&Ws[r][c4] =
            *(const float4*)(Wout + (size_t)(h * DH + r) * Dd + j0 + c4);
    }
    __syncthreads();

    const int tx = tid & 31, ty = tid >> 5;   // d group (8x8), j group (32x4)
    float acc[8][4];
    #pragma unroll
    for (int i = 0; i < 8; i++)
        #pragma unroll
        for (int j = 0; j < 4; j++) acc[i][j] = 0.0f;

    for (int c = 0; c < DH; c++) {
        float4 wv = *(float4*)&Ws[c][tx * 4];
        #pragma unroll
        for (int i = 0; i < 8; i++) {
            float a = Asm[c * DH + ty * 8 + i];
            acc[i][0] += a * wv.x;
            acc[i][1] += a * wv.y;
            acc[i][2] += a * wv.z;
            acc[i][3] += a * wv.w;
        }
    }

    float* Mp = M + (size_t)b * Dd * Dd;
    #pragma unroll
    for (int i = 0; i < 8; i++) {
        int d = ty * 8 + i;
        *(float4*)(Mp + (size_t)(h * DH + d) * Dd + j0 + tx * 4) =
            make_float4(acc[i][0], acc[i][1], acc[i][2], acc[i][3]);
    }
}

// K5: out_b = V_b @ M_b   (per-batch 8192x1024x1024)
__global__ __launch_bounds__(256, 2)
void out_gemm(const float* __restrict__ V,
              const float* __restrict__ M,
              float* __restrict__ out)
{
    const size_t boff = (size_t)blockIdx.z * Nt * Dd;
    sgemm1024(V + boff, M + (size_t)blockIdx.z * Dd * Dd, out + boff,
              blockIdx.y * 128, blockIdx.x * 128);
}

// ---------------------------------------------------------------------------
extern "C" void kernel_launch(void* const* d_in, const int* in_sizes, int n_in,
                              void* d_out, int out_size)
{
    const float* x    = (const float*)d_in[0];
    const float* Wqk  = (const float*)d_in[1];
    const float* Wv   = (const float*)d_in[2];
    const float* Wout = (const float*)d_in[3];
    const float* tau  = (const float*)d_in[4];
    float* out = (float*)d_out;

    void *pqk, *pv, *pg, *pa, *pm;
    cudaGetSymbolAddress(&pqk, g_qk);
    cudaGetSymbolAddress(&pv,  g_v);
    cudaGetSymbolAddress(&pg,  g_gpart);
    cudaGetSymbolAddress(&pa,  g_attn);
    cudaGetSymbolAddress(&pm,  g_m);

    float* QK = (float*)pqk;
    float* V  = (float*)pv;
    float* Gp = (float*)pg;
    float* At = (float*)pa;
    float* Mm = (float*)pm;

    // K1/K2: projections (z = 0 -> QK, z = 1 -> V)
    proj_kernel<<<dim3(8, 128, 2), 256>>>(x, Wqk, Wv, QK, V);
    // K3: partial Gram matrices
    gram_partial<<<dim3(32, NSPLIT), 256>>>(QK, Gp);
    // K4a: reduce + softmax
    softmax_kernel<<<32, 256>>>(Gp, tau, At);
    // K4b: fold attn into output weights
    build_m<<<dim3(8, 32), 256>>>(At, Wout, Mm);
    // K5: final per-batch GEMM
    out_gemm<<<dim3(8, 64, 2), 256>>>(V, Mm, out);
}

// round 3
// speedup vs baseline: 1.0975x; 1.0975x over previous
#include <cuda_runtime.h>
#include <cstdint>
#include <cstddef>

// Problem constants
#define Bq   2
#define Nt   8192
#define Dd   1024
#define Hh   16
#define DH   64
#define Mrows (Bq * Nt)          // 16384
#define NSPLIT 16

// ---------------- scratch ---------------------------------------------------
__device__ float g_qk[(size_t)Mrows * Dd];              // 64 MB
__device__ float g_v [(size_t)Mrows * Dd];              // 64 MB
__device__ float g_wt[(size_t)2 * Dd * Dd];             // 8 MB (WqkT, WvT)
__device__ float g_gpart[(size_t)Bq * Hh * NSPLIT * DH * DH];
__device__ float g_attn [(size_t)Bq * Hh * DH * DH];
__device__ float g_m    [(size_t)Bq * Dd * Dd];         // holds M^T per batch

// ---------------- helpers ----------------------------------------------------
__device__ __forceinline__ float t32(float x) {
    uint32_t u;
    asm("cvt.rna.tf32.f32 %0, %1;" : "=r"(u) : "f"(x));
    return __uint_as_float(u);
}

__device__ __forceinline__ void mma8(float* c, const uint32_t* a, const uint32_t* b) {
    asm volatile(
        "mma.sync.aligned.m16n8k8.row.col.f32.tf32.tf32.f32 "
        "{%0,%1,%2,%3}, {%4,%5,%6,%7}, {%8,%9}, {%0,%1,%2,%3};"
        : "+f"(c[0]), "+f"(c[1]), "+f"(c[2]), "+f"(c[3])
        : "r"(a[0]), "r"(a[1]), "r"(a[2]), "r"(a[3]), "r"(b[0]), "r"(b[1]));
}

// ---------------- 3xTF32 mma.sync GEMM ---------------------------------------
// C[m,n] = sum_k A[m,k]*BT[n,k];  A (rows x 1024) row-major, BT (1024 x 1024)
// row-major (n-major).  Tile 128x128, BK=16, 256 threads, 8 warps (2x4).
#define PADK 20
#define PLANE (128 * PADK)        // floats per plane (2560)
#define BUFF  (4 * PLANE)         // Ah, Al, Bh, Bl
#define SMB   (2 * BUFF * 4)      // bytes = 81920

__global__ __launch_bounds__(256)
void mma_gemm(const float* __restrict__ A0, const float* __restrict__ A1,
              const float* __restrict__ B0, const float* __restrict__ B1,
              float* __restrict__ C0, float* __restrict__ C1)
{
    extern __shared__ float sm[];
    const float* A  = blockIdx.z ? A1 : A0;
    const float* BT = blockIdx.z ? B1 : B0;
    float*       C  = blockIdx.z ? C1 : C0;

    const int bm = blockIdx.y * 128;
    const int bn = blockIdx.x * 128;
    const int tid = threadIdx.x;
    const int wid = tid >> 5;
    const int lid = tid & 31;
    const int g = lid >> 2;          // group id 0..7
    const int t = lid & 3;           // thread-in-group
    const int wm = (wid >> 2) * 64;  // warp m offset
    const int wn = (wid & 3) * 32;   // warp n offset

    // per-thread global-load geometry (2 float4 each for A and B per chunk)
    const int r0  = tid >> 1;              // 0..127
    const int c40 = (tid & 1) * 8;         // 0 or 8
    const float* agp = A  + (size_t)(bm + r0) * 1024 + c40;
    const float* bgp = BT + (size_t)(bn + r0) * 1024 + c40;

    float acc[4][4][4];
    #pragma unroll
    for (int i = 0; i < 4; i++)
        #pragma unroll
        for (int j = 0; j < 4; j++)
            #pragma unroll
            for (int e = 0; e < 4; e++) acc[i][j][e] = 0.0f;

    float4 va0, va1, vb0, vb1;
    auto gload = [&](int k0) {
        va0 = *(const float4*)(agp + k0);
        va1 = *(const float4*)(agp + k0 + 4);
        vb0 = *(const float4*)(bgp + k0);
        vb1 = *(const float4*)(bgp + k0 + 4);
    };
    auto sts = [&](int buf) {
        float* base = sm + buf * BUFF;
        float* Ah = base;
        float* Al = base + PLANE;
        float* Bh = base + 2 * PLANE;
        float* Bl = base + 3 * PLANE;
        int o = r0 * PADK + c40;
        float4 h, l;
        h.x = t32(va0.x); h.y = t32(va0.y); h.z = t32(va0.z); h.w = t32(va0.w);
        l.x = t32(va0.x - h.x); l.y = t32(va0.y - h.y);
        l.z = t32(va0.z - h.z); l.w = t32(va0.w - h.w);
        *(float4*)(Ah + o) = h; *(float4*)(Al + o) = l;
        h.x = t32(va1.x); h.y = t32(va1.y); h.z = t32(va1.z); h.w = t32(va1.w);
        l.x = t32(va1.x - h.x); l.y = t32(va1.y - h.y);
        l.z = t32(va1.z - h.z); l.w = t32(va1.w - h.w);
        *(float4*)(Ah + o + 4) = h; *(float4*)(Al + o + 4) = l;
        h.x = t32(vb0.x); h.y = t32(vb0.y); h.z = t32(vb0.z); h.w = t32(vb0.w);
        l.x = t32(vb0.x - h.x); l.y = t32(vb0.y - h.y);
        l.z = t32(vb0.z - h.z); l.w = t32(vb0.w - h.w);
        *(float4*)(Bh + o) = h; *(float4*)(Bl + o) = l;
        h.x = t32(vb1.x); h.y = t32(vb1.y); h.z = t32(vb1.z); h.w = t32(vb1.w);
        l.x = t32(vb1.x - h.x); l.y = t32(vb1.y - h.y);
        l.z = t32(vb1.z - h.z); l.w = t32(vb1.w - h.w);
        *(float4*)(Bh + o + 4) = h; *(float4*)(Bl + o + 4) = l;
    };
    auto compute = [&](int buf) {
        const float* base = sm + buf * BUFF;
        const float* Ah = base;
        const float* Al = base + PLANE;
        const float* Bh = base + 2 * PLANE;
        const float* Bl = base + 3 * PLANE;
        #pragma unroll
        for (int ks = 0; ks < 16; ks += 8) {
            uint32_t ah[4][4], al[4][4], bh[4][2], bl[4][2];
            #pragma unroll
            for (int i = 0; i < 4; i++) {
                int ra = (wm + i * 16 + g) * PADK + ks + t;
                int rb = ra + 8 * PADK;
                ah[i][0] = __float_as_uint(Ah[ra]);
                ah[i][1] = __float_as_uint(Ah[rb]);
                ah[i][2] = __float_as_uint(Ah[ra + 4]);
                ah[i][3] = __float_as_uint(Ah[rb + 4]);
                al[i][0] = __float_as_uint(Al[ra]);
                al[i][1] = __float_as_uint(Al[rb]);
                al[i][2] = __float_as_uint(Al[ra + 4]);
                al[i][3] = __float_as_uint(Al[rb + 4]);
            }
            #pragma unroll
            for (int j = 0; j < 4; j++) {
                int rb = (wn + j * 8 + g) * PADK + ks + t;
                bh[j][0] = __float_as_uint(Bh[rb]);
                bh[j][1] = __float_as_uint(Bh[rb + 4]);
                bl[j][0] = __float_as_uint(Bl[rb]);
                bl[j][1] = __float_as_uint(Bl[rb + 4]);
            }
            // small terms first, then hi*hi
            #pragma unroll
            for (int i = 0; i < 4; i++)
                #pragma unroll
                for (int j = 0; j < 4; j++) mma8(acc[i][j], ah[i], bl[j]);
            #pragma unroll
            for (int i = 0; i < 4; i++)
                #pragma unroll
                for (int j = 0; j < 4; j++) mma8(acc[i][j], al[i], bh[j]);
            #pragma unroll
            for (int i = 0; i < 4; i++)
                #pragma unroll
                for (int j = 0; j < 4; j++) mma8(acc[i][j], ah[i], bh[j]);
        }
    };

    const int NS = 1024 / 16;   // 64 chunks

    gload(0);
    sts(0);
    __syncthreads();

    for (int s = 0; s < NS; s++) {
        if (s + 1 < NS) gload((s + 1) * 16);
        compute(s & 1);
        __syncthreads();
        if (s + 1 < NS) {
            sts((s + 1) & 1);
            __syncthreads();
        }
    }

    // epilogue
    #pragma unroll
    for (int i = 0; i < 4; i++) {
        int row = bm + wm + i * 16 + g;
        #pragma unroll
        for (int j = 0; j < 4; j++) {
            int col = bn + wn + j * 8 + 2 * t;
            float* cp0 = C + (size_t)row * 1024 + col;
            float* cp1 = C + (size_t)(row + 8) * 1024 + col;
            cp0[0] = acc[i][j][0]; cp0[1] = acc[i][j][1];
            cp1[0] = acc[i][j][2]; cp1[1] = acc[i][j][3];
        }
    }
}

// ---------------- weight transpose: WT[n,k] = W[k,n] -------------------------
__global__ __launch_bounds__(256)
void transpose_w(const float* __restrict__ Wqk, const float* __restrict__ Wv,
                 float* __restrict__ WT)
{
    __shared__ float tbuf[32][33];
    const float* S = blockIdx.z ? Wv : Wqk;
    float* D = WT + (size_t)blockIdx.z * Dd * Dd;
    int bx = blockIdx.x * 32, by = blockIdx.y * 32;
    int tx = threadIdx.x & 31, ty = threadIdx.x >> 5;
    #pragma unroll
    for (int i = 0; i < 4; i++) {
        int r = ty + i * 8;
        tbuf[r][tx] = S[(size_t)(by + r) * Dd + bx + tx];
    }
    __syncthreads();
    #pragma unroll
    for (int i = 0; i < 4; i++) {
        int r = ty + i * 8;
        D[(size_t)(bx + r) * Dd + by + tx] = tbuf[tx][r];
    }
}

// ---------------- Gram partials (fp32) ---------------------------------------
__global__ __launch_bounds__(256)
void gram_partial(const float* __restrict__ QK, float* __restrict__ Gpart)
{
    const int bh = blockIdx.x;
    const int sp = blockIdx.y;
    const int b = bh >> 4;
    const int h = bh & 15;
    const float* A = QK + (size_t)b * Nt * Dd + h * DH;

    __shared__ float As[32][64];
    const int tid = threadIdx.x;
    const int tx = tid & 15, ty = tid >> 4;

    float acc[4][4];
    #pragma unroll
    for (int i = 0; i < 4; i++)
        #pragma unroll
        for (int j = 0; j < 4; j++) acc[i][j] = 0.0f;

    const int n0base = sp * (Nt / NSPLIT);
    for (int n0 = n0base; n0 < n0base + Nt / NSPLIT; n0 += 32) {
        #pragma unroll
        for (int i = 0; i < 2; i++) {
            int idx = tid + i * 256;
            int r = idx >> 4;
            int c4 = (idx & 15) * 4;
            *(float4*)&As[r][c4] = *(const float4*)(A + (size_t)(n0 + r) * Dd + c4);
        }
        __syncthreads();
        #pragma unroll
        for (int kk = 0; kk < 32; kk++) {
            float rc[4], rd[4];
            #pragma unroll
            for (int i = 0; i < 4; i++) rc[i] = As[kk][ty * 4 + i];
            #pragma unroll
            for (int j = 0; j < 4; j++) rd[j] = As[kk][tx * 4 + j];
            #pragma unroll
            for (int i = 0; i < 4; i++)
                #pragma unroll
                for (int j = 0; j < 4; j++)
                    acc[i][j] += rc[i] * rd[j];
        }
        __syncthreads();
    }

    float* gp = Gpart + ((size_t)bh * NSPLIT + sp) * (DH * DH);
    #pragma unroll
    for (int i = 0; i < 4; i++)
        #pragma unroll
        for (int j = 0; j < 4; j++)
            gp[(ty * 4 + i) * DH + tx * 4 + j] = acc[i][j];
}

// ---------------- reduce + softmax --------------------------------------------
__global__ __launch_bounds__(256)
void softmax_kernel(const float* __restrict__ Gpart,
                    const float* __restrict__ tau,
                    float* __restrict__ attn)
{
    const int bh = blockIdx.x;
    const int h = bh & 15;
    __shared__ float G[DH * DH];
    const int tid = threadIdx.x;

    const float* base = Gpart + (size_t)bh * NSPLIT * (DH * DH);
    for (int e = tid; e < DH * DH; e += 256) {
        float s = 0.0f;
        #pragma unroll
        for (int p = 0; p < NSPLIT; p++) s += base[(size_t)p * (DH * DH) + e];
        G[e] = s;
    }
    __syncthreads();

    if (tid < DH) {
        const int c = tid;
        const float tauh = tau[h];
        const float scale = 0.011048543456039806f;  // 1/sqrt(8192)
        const float qc = G[c * DH + c];
        float l[DH];
        float mx = -1e30f;
        #pragma unroll 8
        for (int d = 0; d < DH; d++) {
            float v = (2.0f * G[c * DH + d] - qc - G[d * DH + d]) * scale * tauh;
            l[d] = v;
            mx = fmaxf(mx, v);
        }
        float sum = 0.0f;
        #pragma unroll 8
        for (int d = 0; d < DH; d++) { float e = __expf(l[d] - mx); l[d] = e; sum += e; }
        const float inv = 1.0f / sum;
        float* ap = attn + (size_t)bh * (DH * DH) + c * DH;
        #pragma unroll 8
        for (int d = 0; d < DH; d++) ap[d] = l[d] * inv;
    }
}

// ---------------- fold attn into W_out, emit M^T ------------------------------
// MT_b[j, h*64+d] = sum_c attn[bh][c,d] * Wout[h*64+c, j]
__global__ __launch_bounds__(256)
void build_mT(const float* __restrict__ attn,
              const float* __restrict__ Wout,
              float* __restrict__ MT)
{
    const int bh = blockIdx.y;
    const int b = bh >> 4, h = bh & 15;
    const int j0 = blockIdx.x * 128;

    __shared__ float Asm[DH * DH];
    __shared__ float Ws[DH][128];

    const int tid = threadIdx.x;
    const float* ap = attn + (size_t)bh * (DH * DH);
    for (int e = tid; e < DH * DH; e += 256) Asm[e] = ap[e];

    #pragma unroll
    for (int i = 0; i < 8; i++) {
        int idx = tid + i * 256;
        int r = idx >> 5;
        int c4 = (idx & 31) * 4;
        *(float4*)&Ws[r][c4] =
            *(const float4*)(Wout + (size_t)(h * DH + r) * Dd + j0 + c4);
    }
    __syncthreads();

    const int tx = tid & 15, ty = tid >> 4;   // tx -> d group (4), ty -> j group (8)
    float acc[8][4];
    #pragma unroll
    for (int i = 0; i < 8; i++)
        #pragma unroll
        for (int j = 0; j < 4; j++) acc[i][j] = 0.0f;

    for (int c = 0; c < DH; c++) {
        float4 av = *(float4*)&Asm[c * DH + tx * 4];
        #pragma unroll
        for (int i = 0; i < 8; i++) {
            float w = Ws[c][ty * 8 + i];
            acc[i][0] += w * av.x;
            acc[i][1] += w * av.y;
            acc[i][2] += w * av.z;
            acc[i][3] += w * av.w;
        }
    }

    float* Mp = MT + (size_t)b * Dd * Dd;
    #pragma unroll
    for (int i = 0; i < 8; i++) {
        int j = j0 + ty * 8 + i;
        *(float4*)(Mp + (size_t)j * Dd + h * DH + tx * 4) =
            make_float4(acc[i][0], acc[i][1], acc[i][2], acc[i][3]);
    }
}

// -------------------------------------------------------------------------------
extern "C" void kernel_launch(void* const* d_in, const int* in_sizes, int n_in,
                              void* d_out, int out_size)
{
    const float* x    = (const float*)d_in[0];
    const float* Wqk  = (const float*)d_in[1];
    const float* Wv   = (const float*)d_in[2];
    const float* Wout = (const float*)d_in[3];
    const float* tau  = (const float*)d_in[4];
    float* out = (float*)d_out;

    void *pqk, *pv, *pwt, *pg, *pa, *pm;
    cudaGetSymbolAddress(&pqk, g_qk);
    cudaGetSymbolAddress(&pv,  g_v);
    cudaGetSymbolAddress(&pwt, g_wt);
    cudaGetSymbolAddress(&pg,  g_gpart);
    cudaGetSymbolAddress(&pa,  g_attn);
    cudaGetSymbolAddress(&pm,  g_m);

    float* QK = (float*)pqk;
    float* V  = (float*)pv;
    float* WT = (float*)pwt;
    float* Gp = (float*)pg;
    float* At = (float*)pa;
    float* MT = (float*)pm;

    cudaFuncSetAttribute(mma_gemm, cudaFuncAttributeMaxDynamicSharedMemorySize, SMB);

    // 0: transpose weights to n-major
    transpose_w<<<dim3(32, 32, 2), 256>>>(Wqk, Wv, WT);
    // 1: projections  QK = X @ Wqk, V = X @ Wv  (3xTF32 mma.sync)
    mma_gemm<<<dim3(8, 128, 2), 256, SMB>>>(x, x, WT, WT + (size_t)Dd * Dd, QK, V);
    // 2: Gram partials (fp32)
    gram_partial<<<dim3(32, NSPLIT), 256>>>(QK, Gp);
    // 3: reduce + softmax
    softmax_kernel<<<32, 256>>>(Gp, tau, At);
    // 4: fold attn into W_out, transposed
    build_mT<<<dim3(8, 32), 256>>>(At, Wout, MT);
    // 5: out_b = V_b @ M_b  (3xTF32 mma.sync)
    mma_gemm<<<dim3(8, 64, 2), 256, SMB>>>(V, V + (size_t)Nt * Dd,
                                           MT, MT + (size_t)Dd * Dd,
                                           out, out + (size_t)Nt * Dd);
}

// round 4
// speedup vs baseline: 1.7712x; 1.6138x over previous
#include <cuda_runtime.h>
#include <cuda_bf16.h>
#include <cstdint>
#include <cstddef>

// Problem constants
#define Bq   2
#define Nt   8192
#define Dd   1024
#define Hh   16
#define DH   64
#define Mrows (Bq * Nt)
#define NSPLIT 16

// ---------------- scratch ---------------------------------------------------
__device__ float g_qk[(size_t)Mrows * Dd];
__device__ float g_v [(size_t)Mrows * Dd];
__device__ float g_wt[(size_t)2 * Dd * Dd];
__device__ float g_gpart[(size_t)Bq * Hh * NSPLIT * DH * DH];
__device__ float g_attn [(size_t)Bq * Hh * DH * DH];
__device__ float g_m    [(size_t)Bq * Dd * Dd];

// ---------------- helpers ----------------------------------------------------
__device__ __forceinline__ uint32_t smem_u32(const void* p) {
    uint32_t a;
    asm("{ .reg .u64 t; cvta.to.shared.u64 t, %1; cvt.u32.u64 %0, t; }"
        : "=r"(a) : "l"(p));
    return a;
}

__device__ __forceinline__ void split2(float a, float b, uint32_t& h, uint32_t& l) {
    __nv_bfloat16 ha = __float2bfloat16_rn(a);
    __nv_bfloat16 hb = __float2bfloat16_rn(b);
    __nv_bfloat16 la = __float2bfloat16_rn(a - __bfloat162float(ha));
    __nv_bfloat16 lb = __float2bfloat16_rn(b - __bfloat162float(hb));
    h = (uint32_t)__bfloat16_as_ushort(ha) | ((uint32_t)__bfloat16_as_ushort(hb) << 16);
    l = (uint32_t)__bfloat16_as_ushort(la) | ((uint32_t)__bfloat16_as_ushort(lb) << 16);
}

#define LDM4(r, addr)                                                          \
    asm volatile("ldmatrix.sync.aligned.m8n8.x4.shared.b16 {%0,%1,%2,%3}, [%4];" \
        : "=r"((r)[0]), "=r"((r)[1]), "=r"((r)[2]), "=r"((r)[3]) : "r"(addr))

__device__ __forceinline__ void mma16(float* c, const uint32_t* a, const uint32_t* b) {
    asm volatile(
        "mma.sync.aligned.m16n8k16.row.col.f32.bf16.bf16.f32 "
        "{%0,%1,%2,%3}, {%4,%5,%6,%7}, {%8,%9}, {%0,%1,%2,%3};"
        : "+f"(c[0]), "+f"(c[1]), "+f"(c[2]), "+f"(c[3])
        : "r"(a[0]), "r"(a[1]), "r"(a[2]), "r"(a[3]), "r"(b[0]), "r"(b[1]));
}

// ---------------- 3xBF16 mma.sync GEMM ---------------------------------------
// C[m,n] = sum_k A[m,k]*BT[n,k]; A row-major (lda=1024), BT row-major (n-major).
// Tile 128x128, BK=32, 256 threads = 8 warps (2x4); warp tile 64x32.
// smem planes (bf16, 80B row pitch = 40 bf16): Ah, Al, Bh, Bl; double-buffered.
#define BK 32
#define RPITCH_B 80                     // bytes per padded row
#define PLANE_B  (128 * RPITCH_B)       // 10240 bytes
#define BUF_B    (4 * PLANE_B)          // 40960
#define SMB      (2 * BUF_B)            // 81920 bytes

__global__ __launch_bounds__(256)
void mma_gemm(const float* __restrict__ A0, const float* __restrict__ A1,
              const float* __restrict__ B0, const float* __restrict__ B1,
              float* __restrict__ C0, float* __restrict__ C1)
{
    extern __shared__ __align__(16) uint32_t smu[];
    const float* A  = blockIdx.z ? A1 : A0;
    const float* BT = blockIdx.z ? B1 : B0;
    float*       C  = blockIdx.z ? C1 : C0;

    const int bm = blockIdx.y * 128;
    const int bn = blockIdx.x * 128;
    const int tid = threadIdx.x;
    const int wid = tid >> 5;
    const int lid = tid & 31;
    const int g = lid >> 2;
    const int t = lid & 3;
    const int wm = (wid >> 2) * 64;
    const int wn = (wid & 3) * 32;

    const uint32_t sbase = smem_u32(smu);

    // ldmatrix per-lane byte offsets (within a plane)
    const uint32_t a_off = (uint32_t)(wm + (lid & 15)) * RPITCH_B + (uint32_t)(lid >> 4) * 16;
    const uint32_t b_off = (uint32_t)(wn + (lid & 7) + ((lid >> 4) << 3)) * RPITCH_B
                         + (uint32_t)((lid >> 3) & 1) * 16;

    // global load geometry: row r0, 16 consecutive k at kh
    const int r0 = tid >> 1;
    const int kh = (tid & 1) * 16;
    const float* agp = A  + (size_t)(bm + r0) * 1024 + kh;
    const float* bgp = BT + (size_t)(bn + r0) * 1024 + kh;
    const uint32_t sto = (uint32_t)r0 * (RPITCH_B / 4) + (uint32_t)(kh >> 1);  // u32 units

    float acc[4][4][4];
    #pragma unroll
    for (int i = 0; i < 4; i++)
        #pragma unroll
        for (int j = 0; j < 4; j++)
            #pragma unroll
            for (int e = 0; e < 4; e++) acc[i][j][e] = 0.0f;

    float4 va[2], vb[2];
    float4 va2[2], vb2[2];
    auto gload = [&](int k0) {
        va[0]  = *(const float4*)(agp + k0);
        va[1]  = *(const float4*)(agp + k0 + 4);
        va2[0] = *(const float4*)(agp + k0 + 8);
        va2[1] = *(const float4*)(agp + k0 + 12);
        vb[0]  = *(const float4*)(bgp + k0);
        vb[1]  = *(const float4*)(bgp + k0 + 4);
        vb2[0] = *(const float4*)(bgp + k0 + 8);
        vb2[1] = *(const float4*)(bgp + k0 + 12);
    };
    auto sts = [&](int buf) {
        uint32_t* base = smu + (size_t)buf * (BUF_B / 4);
        uint32_t h[8], l[8];
        // A
        split2(va[0].x,  va[0].y,  h[0], l[0]);
        split2(va[0].z,  va[0].w,  h[1], l[1]);
        split2(va[1].x,  va[1].y,  h[2], l[2]);
        split2(va[1].z,  va[1].w,  h[3], l[3]);
        split2(va2[0].x, va2[0].y, h[4], l[4]);
        split2(va2[0].z, va2[0].w, h[5], l[5]);
        split2(va2[1].x, va2[1].y, h[6], l[6]);
        split2(va2[1].z, va2[1].w, h[7], l[7]);
        uint32_t* Ah = base;
        uint32_t* Al = base + PLANE_B / 4;
        *(uint4*)(Ah + sto)     = make_uint4(h[0], h[1], h[2], h[3]);
        *(uint4*)(Ah + sto + 4) = make_uint4(h[4], h[5], h[6], h[7]);
        *(uint4*)(Al + sto)     = make_uint4(l[0], l[1], l[2], l[3]);
        *(uint4*)(Al + sto + 4) = make_uint4(l[4], l[5], l[6], l[7]);
        // B
        split2(vb[0].x,  vb[0].y,  h[0], l[0]);
        split2(vb[0].z,  vb[0].w,  h[1], l[1]);
        split2(vb[1].x,  vb[1].y,  h[2], l[2]);
        split2(vb[1].z,  vb[1].w,  h[3], l[3]);
        split2(vb2[0].x, vb2[0].y, h[4], l[4]);
        split2(vb2[0].z, vb2[0].w, h[5], l[5]);
        split2(vb2[1].x, vb2[1].y, h[6], l[6]);
        split2(vb2[1].z, vb2[1].w, h[7], l[7]);
        uint32_t* Bh = base + 2 * (PLANE_B / 4);
        uint32_t* Bl = base + 3 * (PLANE_B / 4);
        *(uint4*)(Bh + sto)     = make_uint4(h[0], h[1], h[2], h[3]);
        *(uint4*)(Bh + sto + 4) = make_uint4(h[4], h[5], h[6], h[7]);
        *(uint4*)(Bl + sto)     = make_uint4(l[0], l[1], l[2], l[3]);
        *(uint4*)(Bl + sto + 4) = make_uint4(l[4], l[5], l[6], l[7]);
    };
    auto compute = [&](int buf) {
        const uint32_t bb = sbase + (uint32_t)buf * BUF_B;
        #pragma unroll
        for (int ks2 = 0; ks2 < 2; ks2++) {
            const uint32_t ko = (uint32_t)ks2 * 32;   // 16 bf16 = 32 bytes
            uint32_t ah[4][4], al[4][4];
            uint32_t bh[4][2], bl[4][2];
            #pragma unroll
            for (int i = 0; i < 4; i++)
                LDM4(ah[i], bb + a_off + (uint32_t)i * (16 * RPITCH_B) + ko);
            #pragma unroll
            for (int i = 0; i < 4; i++)
                LDM4(al[i], bb + PLANE_B + a_off + (uint32_t)i * (16 * RPITCH_B) + ko);
            #pragma unroll
            for (int jp = 0; jp < 2; jp++) {
                uint32_t r[4];
                LDM4(r, bb + 2 * PLANE_B + b_off + (uint32_t)jp * (16 * RPITCH_B) + ko);
                bh[2 * jp][0] = r[0]; bh[2 * jp][1] = r[1];
                bh[2 * jp + 1][0] = r[2]; bh[2 * jp + 1][1] = r[3];
            }
            #pragma unroll
            for (int jp = 0; jp < 2; jp++) {
                uint32_t r[4];
                LDM4(r, bb + 3 * PLANE_B + b_off + (uint32_t)jp * (16 * RPITCH_B) + ko);
                bl[2 * jp][0] = r[0]; bl[2 * jp][1] = r[1];
                bl[2 * jp + 1][0] = r[2]; bl[2 * jp + 1][1] = r[3];
            }
            #pragma unroll
            for (int i = 0; i < 4; i++)
                #pragma unroll
                for (int j = 0; j < 4; j++) mma16(acc[i][j], ah[i], bl[j]);
            #pragma unroll
            for (int i = 0; i < 4; i++)
                #pragma unroll
                for (int j = 0; j < 4; j++) mma16(acc[i][j], al[i], bh[j]);
            #pragma unroll
            for (int i = 0; i < 4; i++)
                #pragma unroll
                for (int j = 0; j < 4; j++) mma16(acc[i][j], ah[i], bh[j]);
        }
    };

    const int NS = 1024 / BK;   // 32

    gload(0);
    sts(0);
    __syncthreads();

    #pragma unroll 1
    for (int s = 0; s < NS; s++) {
        if (s + 1 < NS) gload((s + 1) * BK);
        compute(s & 1);
        __syncthreads();
        if (s + 1 < NS) {
            sts((s + 1) & 1);
            __syncthreads();
        }
    }

    // epilogue
    #pragma unroll
    for (int i = 0; i < 4; i++) {
        int row = bm + wm + i * 16 + g;
        #pragma unroll
        for (int j = 0; j < 4; j++) {
            int col = bn + wn + j * 8 + 2 * t;
            float* cp0 = C + (size_t)row * 1024 + col;
            float* cp1 = C + (size_t)(row + 8) * 1024 + col;
            *(float2*)cp0 = make_float2(acc[i][j][0], acc[i][j][1]);
            *(float2*)cp1 = make_float2(acc[i][j][2], acc[i][j][3]);
        }
    }
}

// ---------------- weight transpose -------------------------------------------
__global__ __launch_bounds__(256)
void transpose_w(const float* __restrict__ Wqk, const float* __restrict__ Wv,
                 float* __restrict__ WT)
{
    __shared__ float tbuf[32][33];
    const float* S = blockIdx.z ? Wv : Wqk;
    float* D = WT + (size_t)blockIdx.z * Dd * Dd;
    int bx = blockIdx.x * 32, by = blockIdx.y * 32;
    int tx = threadIdx.x & 31, ty = threadIdx.x >> 5;
    #pragma unroll
    for (int i = 0; i < 4; i++) {
        int r = ty + i * 8;
        tbuf[r][tx] = S[(size_t)(by + r) * Dd + bx + tx];
    }
    __syncthreads();
    #pragma unroll
    for (int i = 0; i < 4; i++) {
        int r = ty + i * 8;
        D[(size_t)(bx + r) * Dd + by + tx] = tbuf[tx][r];
    }
}

// ---------------- Gram partials (fp32) ---------------------------------------
__global__ __launch_bounds__(256)
void gram_partial(const float* __restrict__ QK, float* __restrict__ Gpart)
{
    const int bh = blockIdx.x;
    const int sp = blockIdx.y;
    const int b = bh >> 4;
    const int h = bh & 15;
    const float* A = QK + (size_t)b * Nt * Dd + h * DH;

    __shared__ float As[32][64];
    const int tid = threadIdx.x;
    const int tx = tid & 15, ty = tid >> 4;

    float acc[4][4];
    #pragma unroll
    for (int i = 0; i < 4; i++)
        #pragma unroll
        for (int j = 0; j < 4; j++) acc[i][j] = 0.0f;

    const int n0base = sp * (Nt / NSPLIT);
    for (int n0 = n0base; n0 < n0base + Nt / NSPLIT; n0 += 32) {
        #pragma unroll
        for (int i = 0; i < 2; i++) {
            int idx = tid + i * 256;
            int r = idx >> 4;
            int c4 = (idx & 15) * 4;
            *(float4*)&As[r][c4] = *(const float4*)(A + (size_t)(n0 + r) * Dd + c4);
        }
        __syncthreads();
        #pragma unroll
        for (int kk = 0; kk < 32; kk++) {
            float rc[4], rd[4];
            #pragma unroll
            for (int i = 0; i < 4; i++) rc[i] = As[kk][ty * 4 + i];
            #pragma unroll
            for (int j = 0; j < 4; j++) rd[j] = As[kk][tx * 4 + j];
            #pragma unroll
            for (int i = 0; i < 4; i++)
                #pragma unroll
                for (int j = 0; j < 4; j++)
                    acc[i][j] += rc[i] * rd[j];
        }
        __syncthreads();
    }

    float* gp = Gpart + ((size_t)bh * NSPLIT + sp) * (DH * DH);
    #pragma unroll
    for (int i = 0; i < 4; i++)
        #pragma unroll
        for (int j = 0; j < 4; j++)
            gp[(ty * 4 + i) * DH + tx * 4 + j] = acc[i][j];
}

// ---------------- reduce + softmax --------------------------------------------
__global__ __launch_bounds__(256)
void softmax_kernel(const float* __restrict__ Gpart,
                    const float* __restrict__ tau,
                    float* __restrict__ attn)
{
    const int bh = blockIdx.x;
    const int h = bh & 15;
    __shared__ float G[DH * DH];
    const int tid = threadIdx.x;

    const float* base = Gpart + (size_t)bh * NSPLIT * (DH * DH);
    for (int e = tid; e < DH * DH; e += 256) {
        float s = 0.0f;
        #pragma unroll
        for (int p = 0; p < NSPLIT; p++) s += base[(size_t)p * (DH * DH) + e];
        G[e] = s;
    }
    __syncthreads();

    if (tid < DH) {
        const int c = tid;
        const float tauh = tau[h];
        const float scale = 0.011048543456039806f;
        const float qc = G[c * DH + c];
        float l[DH];
        float mx = -1e30f;
        #pragma unroll 8
        for (int d = 0; d < DH; d++) {
            float v = (2.0f * G[c * DH + d] - qc - G[d * DH + d]) * scale * tauh;
            l[d] = v;
            mx = fmaxf(mx, v);
        }
        float sum = 0.0f;
        #pragma unroll 8
        for (int d = 0; d < DH; d++) { float e = __expf(l[d] - mx); l[d] = e; sum += e; }
        const float inv = 1.0f / sum;
        float* ap = attn + (size_t)bh * (DH * DH) + c * DH;
        #pragma unroll 8
        for (int d = 0; d < DH; d++) ap[d] = l[d] * inv;
    }
}

// ---------------- fold attn into W_out, emit M^T ------------------------------
__global__ __launch_bounds__(256)
void build_mT(const float* __restrict__ attn,
              const float* __restrict__ Wout,
              float* __restrict__ MT)
{
    const int bh = blockIdx.y;
    const int b = bh >> 4, h = bh & 15;
    const int j0 = blockIdx.x * 128;

    __shared__ float Asm[DH * DH];
    __shared__ float Ws[DH][128];

    const int tid = threadIdx.x;
    const float* ap = attn + (size_t)bh * (DH * DH);
    for (int e = tid; e < DH * DH; e += 256) Asm[e] = ap[e];

    #pragma unroll
    for (int i = 0; i < 8; i++) {
        int idx = tid + i * 256;
        int r = idx >> 5;
        int c4 = (idx & 31) * 4;
        *(float4*)&Ws[r][c4] =
            *(const float4*)(Wout + (size_t)(h * DH + r) * Dd + j0 + c4);
    }
    __syncthreads();

    const int tx = tid & 15, ty = tid >> 4;
    float acc[8][4];
    #pragma unroll
    for (int i = 0; i < 8; i++)
        #pragma unroll
        for (int j = 0; j < 4; j++) acc[i][j] = 0.0f;

    for (int c = 0; c < DH; c++) {
        float4 av = *(float4*)&Asm[c * DH + tx * 4];
        #pragma unroll
        for (int i = 0; i < 8; i++) {
            float w = Ws[c][ty * 8 + i];
            acc[i][0] += w * av.x;
            acc[i][1] += w * av.y;
            acc[i][2] += w * av.z;
            acc[i][3] += w * av.w;
        }
    }

    float* Mp = MT + (size_t)b * Dd * Dd;
    #pragma unroll
    for (int i = 0; i < 8; i++) {
        int j = j0 + ty * 8 + i;
        *(float4*)(Mp + (size_t)j * Dd + h * DH + tx * 4) =
            make_float4(acc[i][0], acc[i][1], acc[i][2], acc[i][3]);
    }
}

// -------------------------------------------------------------------------------
extern "C" void kernel_launch(void* const* d_in, const int* in_sizes, int n_in,
                              void* d_out, int out_size)
{
    const float* x    = (const float*)d_in[0];
    const float* Wqk  = (const float*)d_in[1];
    const float* Wv   = (const float*)d_in[2];
    const float* Wout = (const float*)d_in[3];
    const float* tau  = (const float*)d_in[4];
    float* out = (float*)d_out;

    void *pqk, *pv, *pwt, *pg, *pa, *pm;
    cudaGetSymbolAddress(&pqk, g_qk);
    cudaGetSymbolAddress(&pv,  g_v);
    cudaGetSymbolAddress(&pwt, g_wt);
    cudaGetSymbolAddress(&pg,  g_gpart);
    cudaGetSymbolAddress(&pa,  g_attn);
    cudaGetSymbolAddress(&pm,  g_m);

    float* QK = (float*)pqk;
    float* V  = (float*)pv;
    float* WT = (float*)pwt;
    float* Gp = (float*)pg;
    float* At = (float*)pa;
    float* MT = (float*)pm;

    cudaFuncSetAttribute(mma_gemm, cudaFuncAttributeMaxDynamicSharedMemorySize, SMB);

    // 0: transpose weights to n-major
    transpose_w<<<dim3(32, 32, 2), 256>>>(Wqk, Wv, WT);
    // 1: projections  QK = X @ Wqk, V = X @ Wv  (3xBF16 mma.sync)
    mma_gemm<<<dim3(8, 128, 2), 256, SMB>>>(x, x, WT, WT + (size_t)Dd * Dd, QK, V);
    // 2: Gram partials (fp32)
    gram_partial<<<dim3(32, NSPLIT), 256>>>(QK, Gp);
    // 3: reduce + softmax
    softmax_kernel<<<32, 256>>>(Gp, tau, At);
    // 4: fold attn into W_out (transposed)
    build_mT<<<dim3(8, 32), 256>>>(At, Wout, MT);
    // 5: out_b = V_b @ M_b  (3xBF16 mma.sync)
    mma_gemm<<<dim3(8, 64, 2), 256, SMB>>>(V, V + (size_t)Nt * Dd,
                                           MT, MT + (size_t)Dd * Dd,
                                           out, out + (size_t)Nt * Dd);
}

// round 5
// speedup vs baseline: 2.5786x; 1.4558x over previous
#include <cuda_runtime.h>
#include <cuda_bf16.h>
#include <cstdint>
#include <cstddef>

typedef __nv_bfloat16 bf16;

// Problem constants
#define Bq   2
#define Nt   8192
#define Dd   1024
#define Hh   16
#define DH   64
#define Mrows (Bq * Nt)
#define NSPLIT 16

// ---------------- scratch ---------------------------------------------------
__device__ float g_qk[(size_t)Mrows * Dd];                 // 64 MB
__device__ bf16  g_xh[(size_t)Mrows * Dd];                 // 32 MB
__device__ bf16  g_xl[(size_t)Mrows * Dd];
__device__ bf16  g_vh[(size_t)Mrows * Dd];
__device__ bf16  g_vl[(size_t)Mrows * Dd];
__device__ bf16  g_wth[(size_t)2 * Dd * Dd];
__device__ bf16  g_wtl[(size_t)2 * Dd * Dd];
__device__ bf16  g_mth[(size_t)Bq * Dd * Dd];
__device__ bf16  g_mtl[(size_t)Bq * Dd * Dd];
__device__ float g_gpart[(size_t)Bq * Hh * NSPLIT * DH * DH];
__device__ float g_attn [(size_t)Bq * Hh * DH * DH];

// ---------------- PTX helpers -------------------------------------------------
__device__ __forceinline__ uint32_t smem_u32(const void* p) {
    uint32_t a;
    asm("{ .reg .u64 t; cvta.to.shared.u64 t, %1; cvt.u32.u64 %0, t; }"
        : "=r"(a) : "l"(p));
    return a;
}

#define LDM4(r, addr)                                                          \
    asm volatile("ldmatrix.sync.aligned.m8n8.x4.shared.b16 {%0,%1,%2,%3}, [%4];" \
        : "=r"((r)[0]), "=r"((r)[1]), "=r"((r)[2]), "=r"((r)[3]) : "r"(addr))

__device__ __forceinline__ void mma16(float* c, const uint32_t* a, const uint32_t* b) {
    asm volatile(
        "mma.sync.aligned.m16n8k16.row.col.f32.bf16.bf16.f32 "
        "{%0,%1,%2,%3}, {%4,%5,%6,%7}, {%8,%9}, {%0,%1,%2,%3};"
        : "+f"(c[0]), "+f"(c[1]), "+f"(c[2]), "+f"(c[3])
        : "r"(a[0]), "r"(a[1]), "r"(a[2]), "r"(a[3]), "r"(b[0]), "r"(b[1]));
}

#define CPA(dst, src) \
    asm volatile("cp.async.cg.shared.global [%0], [%1], 16;" :: "r"(dst), "l"(src) : "memory")
#define CPC() asm volatile("cp.async.commit_group;" ::: "memory")
#define CPW(n) asm volatile("cp.async.wait_group %0;" :: "n"(n) : "memory")

// swizzled byte offset within an 8 KB plane (128 rows x 64 B)
__device__ __forceinline__ uint32_t swz(uint32_t row, uint32_t c) {
    return row * 64u + (((c ^ ((row >> 1) & 3u)) & 3u) << 4);
}

// ---------------- bf16 split GEMM with cp.async pipeline -----------------------
// C[m,n] = sum_k A[m,k]*BT[n,k]; planes Ah/Al row-major (lda=1024), Bh/Bl n-major.
// Tile 128x128, BK=32, 3 stages, 256 threads = 8 warps (2x4), warp tile 64x32.
#define BK 32
#define PLANE_B 8192                 // 128 rows * 64 bytes
#define STAGE_B (4 * PLANE_B)        // 32768
#define NSTAGE  3
#define SMB     (NSTAGE * STAGE_B)   // 98304

__global__ __launch_bounds__(256, 1)
void mma_gemm(const bf16* __restrict__ gAh, const bf16* __restrict__ gAl, size_t aZ,
              const bf16* __restrict__ gBh, const bf16* __restrict__ gBl,
              float* Cf0, float* Cf1, bf16* Ch, bf16* Cl)
{
    extern __shared__ __align__(16) char smc[];
    const int z = blockIdx.z;
    const bf16* Ah = gAh + (size_t)z * aZ;
    const bf16* Al = gAl + (size_t)z * aZ;
    const bf16* Bh = gBh + (size_t)z * Dd * Dd;
    const bf16* Bl = gBl + (size_t)z * Dd * Dd;
    float* Cf = z ? Cf1 : Cf0;

    const int bm = blockIdx.y * 128;
    const int bn = blockIdx.x * 128;
    const int tid = threadIdx.x;
    const int wid = tid >> 5;
    const int lid = tid & 31;
    const int g = lid >> 2;
    const int t = lid & 3;
    const int wm = (wid >> 2) * 64;
    const int wn = (wid & 3) * 32;

    const uint32_t sbase = smem_u32(smc);

    // cp.async geometry: 2 chunks per thread per plane
    const uint32_t r0 = (uint32_t)tid >> 2;          // rows 0..63   (q=0)
    const uint32_t c0 = (uint32_t)tid & 3;
    const uint32_t r1 = r0 + 64;                     // rows 64..127 (q=1)
    const uint32_t sw0 = swz(r0, c0);
    const uint32_t sw1 = swz(r1, c0);
    const bf16* ga0 = Ah + (size_t)(bm + r0) * 1024 + c0 * 8;
    const bf16* ga1 = Ah + (size_t)(bm + r1) * 1024 + c0 * 8;
    const bf16* gal0 = Al + (size_t)(bm + r0) * 1024 + c0 * 8;
    const bf16* gal1 = Al + (size_t)(bm + r1) * 1024 + c0 * 8;
    const bf16* gb0 = Bh + (size_t)(bn + r0) * 1024 + c0 * 8;
    const bf16* gb1 = Bh + (size_t)(bn + r1) * 1024 + c0 * 8;
    const bf16* gbl0 = Bl + (size_t)(bn + r0) * 1024 + c0 * 8;
    const bf16* gbl1 = Bl + (size_t)(bn + r1) * 1024 + c0 * 8;

    auto issue = [&](int k0, int st) {
        uint32_t sb2 = sbase + (uint32_t)st * STAGE_B;
        CPA(sb2 + sw0,               ga0 + k0);
        CPA(sb2 + sw1,               ga1 + k0);
        CPA(sb2 + PLANE_B + sw0,     gal0 + k0);
        CPA(sb2 + PLANE_B + sw1,     gal1 + k0);
        CPA(sb2 + 2 * PLANE_B + sw0, gb0 + k0);
        CPA(sb2 + 2 * PLANE_B + sw1, gb1 + k0);
        CPA(sb2 + 3 * PLANE_B + sw0, gbl0 + k0);
        CPA(sb2 + 3 * PLANE_B + sw1, gbl1 + k0);
    };

    float acc[4][4][4];
    #pragma unroll
    for (int i = 0; i < 4; i++)
        #pragma unroll
        for (int j = 0; j < 4; j++)
            #pragma unroll
            for (int e = 0; e < 4; e++) acc[i][j][e] = 0.0f;

    // precomputed fragment geometry
    uint32_t arow[4], brow[2];
    #pragma unroll
    for (int i = 0; i < 4; i++) arow[i] = (uint32_t)(wm + i * 16 + (lid & 15));
    #pragma unroll
    for (int jp = 0; jp < 2; jp++)
        brow[jp] = (uint32_t)(wn + jp * 16 + (lid & 7) + ((lid >> 4) << 3));
    const uint32_t aco = (uint32_t)(lid >> 4);
    const uint32_t bco = (uint32_t)((lid >> 3) & 1);

    auto compute = [&](int buf) {
        const uint32_t bb = sbase + (uint32_t)buf * STAGE_B;
        #pragma unroll
        for (int ks2 = 0; ks2 < 2; ks2++) {
            uint32_t ah[4][4], al[4][4], bh[4][2], bl[4][2];
            #pragma unroll
            for (int i = 0; i < 4; i++) {
                uint32_t off = swz(arow[i], ks2 * 2 + aco);
                LDM4(ah[i], bb + off);
                LDM4(al[i], bb + PLANE_B + off);
            }
            #pragma unroll
            for (int jp = 0; jp < 2; jp++) {
                uint32_t off = swz(brow[jp], ks2 * 2 + bco);
                uint32_t r[4];
                LDM4(r, bb + 2 * PLANE_B + off);
                bh[2 * jp][0] = r[0]; bh[2 * jp][1] = r[1];
                bh[2 * jp + 1][0] = r[2]; bh[2 * jp + 1][1] = r[3];
                LDM4(r, bb + 3 * PLANE_B + off);
                bl[2 * jp][0] = r[0]; bl[2 * jp][1] = r[1];
                bl[2 * jp + 1][0] = r[2]; bl[2 * jp + 1][1] = r[3];
            }
            #pragma unroll
            for (int i = 0; i < 4; i++)
                #pragma unroll
                for (int j = 0; j < 4; j++) mma16(acc[i][j], ah[i], bl[j]);
            #pragma unroll
            for (int i = 0; i < 4; i++)
                #pragma unroll
                for (int j = 0; j < 4; j++) mma16(acc[i][j], al[i], bh[j]);
            #pragma unroll
            for (int i = 0; i < 4; i++)
                #pragma unroll
                for (int j = 0; j < 4; j++) mma16(acc[i][j], ah[i], bh[j]);
        }
    };

    const int NS = 1024 / BK;   // 32

    issue(0, 0); CPC();
    issue(BK, 1); CPC();

    #pragma unroll 1
    for (int s = 0; s < NS; s++) {
        if (s < NS - 1) { CPW(1); } else { CPW(0); }
        __syncthreads();
        compute(s % 3);
        if (s + 2 < NS) { issue((s + 2) * BK, (s + 2) % 3); CPC(); }
    }

    // epilogue
    if (Cf) {
        #pragma unroll
        for (int i = 0; i < 4; i++) {
            int row = bm + wm + i * 16 + g;
            #pragma unroll
            for (int j = 0; j < 4; j++) {
                int col = bn + wn + j * 8 + 2 * t;
                *(float2*)(Cf + (size_t)row * 1024 + col) =
                    make_float2(acc[i][j][0], acc[i][j][1]);
                *(float2*)(Cf + (size_t)(row + 8) * 1024 + col) =
                    make_float2(acc[i][j][2], acc[i][j][3]);
            }
        }
    } else {
        #pragma unroll
        for (int i = 0; i < 4; i++) {
            int row = bm + wm + i * 16 + g;
            #pragma unroll
            for (int j = 0; j < 4; j++) {
                int col = bn + wn + j * 8 + 2 * t;
                #pragma unroll
                for (int e = 0; e < 2; e++) {
                    float v0 = acc[i][j][2 * e], v1 = acc[i][j][2 * e + 1];
                    bf16 h0 = __float2bfloat16_rn(v0);
                    bf16 h1 = __float2bfloat16_rn(v1);
                    bf16 l0 = __float2bfloat16_rn(v0 - __bfloat162float(h0));
                    bf16 l1 = __float2bfloat16_rn(v1 - __bfloat162float(h1));
                    size_t o = (size_t)(row + 8 * e) * 1024 + col;
                    __nv_bfloat162 hv; hv.x = h0; hv.y = h1;
                    __nv_bfloat162 lv; lv.x = l0; lv.y = l1;
                    *(__nv_bfloat162*)(Ch + o) = hv;
                    *(__nv_bfloat162*)(Cl + o) = lv;
                }
            }
        }
    }
}

// ---------------- split fp32 -> bf16 hi/lo planes ------------------------------
__global__ __launch_bounds__(256)
void split_f32(const float* __restrict__ src, bf16* __restrict__ h, bf16* __restrict__ l)
{
    size_t i = ((size_t)blockIdx.x * 256 + threadIdx.x) * 4;
    float4 v = *(const float4*)(src + i);
    bf16 h0 = __float2bfloat16_rn(v.x), h1 = __float2bfloat16_rn(v.y);
    bf16 h2 = __float2bfloat16_rn(v.z), h3 = __float2bfloat16_rn(v.w);
    bf16 l0 = __float2bfloat16_rn(v.x - __bfloat162float(h0));
    bf16 l1 = __float2bfloat16_rn(v.y - __bfloat162float(h1));
    bf16 l2 = __float2bfloat16_rn(v.z - __bfloat162float(h2));
    bf16 l3 = __float2bfloat16_rn(v.w - __bfloat162float(h3));
    __nv_bfloat162 a, b;
    a.x = h0; a.y = h1; b.x = h2; b.y = h3;
    *(__nv_bfloat162*)(h + i) = a; *(__nv_bfloat162*)(h + i + 2) = b;
    a.x = l0; a.y = l1; b.x = l2; b.y = l3;
    *(__nv_bfloat162*)(l + i) = a; *(__nv_bfloat162*)(l + i + 2) = b;
}

// ---------------- weight transpose + split ------------------------------------
__global__ __launch_bounds__(256)
void transpose_w(const float* __restrict__ Wqk, const float* __restrict__ Wv,
                 bf16* __restrict__ WTh, bf16* __restrict__ WTl)
{
    __shared__ float tbuf[32][33];
    const float* S = blockIdx.z ? Wv : Wqk;
    bf16* Dh = WTh + (size_t)blockIdx.z * Dd * Dd;
    bf16* Dl = WTl + (size_t)blockIdx.z * Dd * Dd;
    int bx = blockIdx.x * 32, by = blockIdx.y * 32;
    int tx = threadIdx.x & 31, ty = threadIdx.x >> 5;
    #pragma unroll
    for (int i = 0; i < 4; i++) {
        int r = ty + i * 8;
        tbuf[r][tx] = S[(size_t)(by + r) * Dd + bx + tx];
    }
    __syncthreads();
    #pragma unroll
    for (int i = 0; i < 4; i++) {
        int r = ty + i * 8;
        float v = tbuf[tx][r];
        bf16 h = __float2bfloat16_rn(v);
        bf16 l = __float2bfloat16_rn(v - __bfloat162float(h));
        size_t o = (size_t)(bx + r) * Dd + by + tx;
        Dh[o] = h; Dl[o] = l;
    }
}

// ---------------- Gram partials (fp32) -----------------------------------------
__global__ __launch_bounds__(256)
void gram_partial(const float* __restrict__ QK, float* __restrict__ Gpart)
{
    const int bh = blockIdx.x;
    const int sp = blockIdx.y;
    const int b = bh >> 4;
    const int h = bh & 15;
    const float* A = QK + (size_t)b * Nt * Dd + h * DH;

    __shared__ float As[32][64];
    const int tid = threadIdx.x;
    const int tx = tid & 15, ty = tid >> 4;

    float acc[4][4];
    #pragma unroll
    for (int i = 0; i < 4; i++)
        #pragma unroll
        for (int j = 0; j < 4; j++) acc[i][j] = 0.0f;

    const int n0base = sp * (Nt / NSPLIT);
    for (int n0 = n0base; n0 < n0base + Nt / NSPLIT; n0 += 32) {
        #pragma unroll
        for (int i = 0; i < 2; i++) {
            int idx = tid + i * 256;
            int r = idx >> 4;
            int c4 = (idx & 15) * 4;
            *(float4*)&As[r][c4] = *(const float4*)(A + (size_t)(n0 + r) * Dd + c4);
        }
        __syncthreads();
        #pragma unroll
        for (int kk = 0; kk < 32; kk++) {
            float rc[4], rd[4];
            #pragma unroll
            for (int i = 0; i < 4; i++) rc[i] = As[kk][ty * 4 + i];
            #pragma unroll
            for (int j = 0; j < 4; j++) rd[j] = As[kk][tx * 4 + j];
            #pragma unroll
            for (int i = 0; i < 4; i++)
                #pragma unroll
                for (int j = 0; j < 4; j++)
                    acc[i][j] += rc[i] * rd[j];
        }
        __syncthreads();
    }

    float* gp = Gpart + ((size_t)bh * NSPLIT + sp) * (DH * DH);
    #pragma unroll
    for (int i = 0; i < 4; i++)
        #pragma unroll
        for (int j = 0; j < 4; j++)
            gp[(ty * 4 + i) * DH + tx * 4 + j] = acc[i][j];
}

// ---------------- reduce + softmax ----------------------------------------------
__global__ __launch_bounds__(256)
void softmax_kernel(const float* __restrict__ Gpart,
                    const float* __restrict__ tau,
                    float* __restrict__ attn)
{
    const int bh = blockIdx.x;
    const int h = bh & 15;
    __shared__ float G[DH * DH];
    const int tid = threadIdx.x;

    const float* base = Gpart + (size_t)bh * NSPLIT * (DH * DH);
    for (int e = tid; e < DH * DH; e += 256) {
        float s = 0.0f;
        #pragma unroll
        for (int p = 0; p < NSPLIT; p++) s += base[(size_t)p * (DH * DH) + e];
        G[e] = s;
    }
    __syncthreads();

    if (tid < DH) {
        const int c = tid;
        const float tauh = tau[h];
        const float scale = 0.011048543456039806f;
        const float qc = G[c * DH + c];
        float l[DH];
        float mx = -1e30f;
        #pragma unroll 8
        for (int d = 0; d < DH; d++) {
            float v = (2.0f * G[c * DH + d] - qc - G[d * DH + d]) * scale * tauh;
            l[d] = v;
            mx = fmaxf(mx, v);
        }
        float sum = 0.0f;
        #pragma unroll 8
        for (int d = 0; d < DH; d++) { float e = __expf(l[d] - mx); l[d] = e; sum += e; }
        const float inv = 1.0f / sum;
        float* ap = attn + (size_t)bh * (DH * DH) + c * DH;
        #pragma unroll 8
        for (int d = 0; d < DH; d++) ap[d] = l[d] * inv;
    }
}

// ---------------- fold attn into W_out, emit split M^T ---------------------------
// MT_b[j, h*64+d] = sum_c attn[bh][c,d] * Wout[h*64+c, j]
__global__ __launch_bounds__(256)
void build_mT(const float* __restrict__ attn,
              const float* __restrict__ Wout,
              bf16* __restrict__ MTh, bf16* __restrict__ MTl)
{
    const int bh = blockIdx.y;
    const int b = bh >> 4, h = bh & 15;
    const int j0 = blockIdx.x * 128;

    __shared__ float Asm[DH * DH];
    __shared__ float Ws[DH][128];

    const int tid = threadIdx.x;
    const float* ap = attn + (size_t)bh * (DH * DH);
    for (int e = tid; e < DH * DH; e += 256) Asm[e] = ap[e];

    #pragma unroll
    for (int i = 0; i < 8; i++) {
        int idx = tid + i * 256;
        int r = idx >> 5;
        int c4 = (idx & 31) * 4;
        *(float4*)&Ws[r][c4] =
            *(const float4*)(Wout + (size_t)(h * DH + r) * Dd + j0 + c4);
    }
    __syncthreads();

    const int tx = tid & 15, ty = tid >> 4;
    float acc[8][4];
    #pragma unroll
    for (int i = 0; i < 8; i++)
        #pragma unroll
        for (int j = 0; j < 4; j++) acc[i][j] = 0.0f;

    for (int c = 0; c < DH; c++) {
        float4 av = *(float4*)&Asm[c * DH + tx * 4];
        #pragma unroll
        for (int i = 0; i < 8; i++) {
            float w = Ws[c][ty * 8 + i];
            acc[i][0] += w * av.x;
            acc[i][1] += w * av.y;
            acc[i][2] += w * av.z;
            acc[i][3] += w * av.w;
        }
    }

    bf16* Mh = MTh + (size_t)b * Dd * Dd;
    bf16* Ml = MTl + (size_t)b * Dd * Dd;
    #pragma unroll
    for (int i = 0; i < 8; i++) {
        int j = j0 + ty * 8 + i;
        size_t o = (size_t)j * Dd + h * DH + tx * 4;
        #pragma unroll
        for (int e = 0; e < 4; e++) {
            float v = acc[i][e];
            bf16 hh = __float2bfloat16_rn(v);
            bf16 ll = __float2bfloat16_rn(v - __bfloat162float(hh));
            Mh[o + e] = hh; Ml[o + e] = ll;
        }
    }
}

// ----------------------------------------------------------------------------------
extern "C" void kernel_launch(void* const* d_in, const int* in_sizes, int n_in,
                              void* d_out, int out_size)
{
    const float* x    = (const float*)d_in[0];
    const float* Wqk  = (const float*)d_in[1];
    const float* Wv   = (const float*)d_in[2];
    const float* Wout = (const float*)d_in[3];
    const float* tau  = (const float*)d_in[4];
    float* out = (float*)d_out;

    void *pqk, *pxh, *pxl, *pvh, *pvl, *pwth, *pwtl, *pmth, *pmtl, *pg, *pa;
    cudaGetSymbolAddress(&pqk, g_qk);
    cudaGetSymbolAddress(&pxh, g_xh);
    cudaGetSymbolAddress(&pxl, g_xl);
    cudaGetSymbolAddress(&pvh, g_vh);
    cudaGetSymbolAddress(&pvl, g_vl);
    cudaGetSymbolAddress(&pwth, g_wth);
    cudaGetSymbolAddress(&pwtl, g_wtl);
    cudaGetSymbolAddress(&pmth, g_mth);
    cudaGetSymbolAddress(&pmtl, g_mtl);
    cudaGetSymbolAddress(&pg, g_gpart);
    cudaGetSymbolAddress(&pa, g_attn);

    float* QK = (float*)pqk;
    bf16 *Xh = (bf16*)pxh, *Xl = (bf16*)pxl;
    bf16 *Vh = (bf16*)pvh, *Vl = (bf16*)pvl;
    bf16 *WTh = (bf16*)pwth, *WTl = (bf16*)pwtl;
    bf16 *MTh = (bf16*)pmth, *MTl = (bf16*)pmtl;
    float* Gp = (float*)pg;
    float* At = (float*)pa;

    cudaFuncSetAttribute(mma_gemm, cudaFuncAttributeMaxDynamicSharedMemorySize, SMB);

    // 0a: split X into bf16 hi/lo planes
    split_f32<<<(size_t)Mrows * Dd / 1024, 256>>>(x, Xh, Xl);
    // 0b: transpose + split weights (n-major)
    transpose_w<<<dim3(32, 32, 2), 256>>>(Wqk, Wv, WTh, WTl);
    // 1: projections; z=0 -> QK (fp32), z=1 -> V (split bf16 planes)
    mma_gemm<<<dim3(8, 128, 2), 256, SMB>>>(Xh, Xl, 0,
                                            WTh, WTl,
                                            QK, nullptr, Vh, Vl);
    // 2: Gram partials (fp32)
    gram_partial<<<dim3(32, NSPLIT), 256>>>(QK, Gp);
    // 3: reduce + softmax
    softmax_kernel<<<32, 256>>>(Gp, tau, At);
    // 4: fold attn into W_out (transposed, split)
    build_mT<<<dim3(8, 32), 256>>>(At, Wout, MTh, MTl);
    // 5: out_b = V_b @ M_b
    mma_gemm<<<dim3(8, 64, 2), 256, SMB>>>(Vh, Vl, (size_t)Nt * Dd,
                                           MTh, MTl,
                                           out, out + (size_t)Nt * Dd, nullptr, nullptr);
}

// round 6
// speedup vs baseline: 2.6707x; 1.0357x over previous
#include <cuda_runtime.h>
#include <cuda_bf16.h>
#include <cstdint>
#include <cstddef>

typedef __nv_bfloat16 bf16;

// Problem constants
#define Bq   2
#define Nt   8192
#define Dd   1024
#define Hh   16
#define DH   64
#define Mrows (Bq * Nt)
#define NSPLIT 16

// ---------------- scratch ---------------------------------------------------
__device__ float g_qk[(size_t)Mrows * Dd];
__device__ bf16  g_xh[(size_t)Mrows * Dd];
__device__ bf16  g_xl[(size_t)Mrows * Dd];
__device__ bf16  g_vh[(size_t)Mrows * Dd];
__device__ bf16  g_vl[(size_t)Mrows * Dd];
__device__ bf16  g_wth[(size_t)2 * Dd * Dd];
__device__ bf16  g_wtl[(size_t)2 * Dd * Dd];
__device__ bf16  g_mth[(size_t)Bq * Dd * Dd];
__device__ bf16  g_mtl[(size_t)Bq * Dd * Dd];
__device__ float g_gpart[(size_t)Bq * Hh * NSPLIT * DH * DH];
__device__ float g_attn [(size_t)Bq * Hh * DH * DH];

// ---------------- PTX helpers -------------------------------------------------
__device__ __forceinline__ uint32_t smem_u32(const void* p) {
    uint32_t a;
    asm("{ .reg .u64 t; cvta.to.shared.u64 t, %1; cvt.u32.u64 %0, t; }"
        : "=r"(a) : "l"(p));
    return a;
}

#define LDM4(r, addr)                                                          \
    asm volatile("ldmatrix.sync.aligned.m8n8.x4.shared.b16 {%0,%1,%2,%3}, [%4];" \
        : "=r"((r)[0]), "=r"((r)[1]), "=r"((r)[2]), "=r"((r)[3]) : "r"(addr))

__device__ __forceinline__ void mma16(float* c, const uint32_t* a, const uint32_t* b) {
    asm volatile(
        "mma.sync.aligned.m16n8k16.row.col.f32.bf16.bf16.f32 "
        "{%0,%1,%2,%3}, {%4,%5,%6,%7}, {%8,%9}, {%0,%1,%2,%3};"
        : "+f"(c[0]), "+f"(c[1]), "+f"(c[2]), "+f"(c[3])
        : "r"(a[0]), "r"(a[1]), "r"(a[2]), "r"(a[3]), "r"(b[0]), "r"(b[1]));
}

#define CPA(dst, src) \
    asm volatile("cp.async.cg.shared.global [%0], [%1], 16;" :: "r"(dst), "l"(src) : "memory")
#define CPC() asm volatile("cp.async.commit_group;" ::: "memory")
#define CPW(n) asm volatile("cp.async.wait_group %0;" :: "n"(n) : "memory")

// swizzled byte offset within a plane (rows x 64 B)
__device__ __forceinline__ uint32_t swz(uint32_t row, uint32_t c) {
    return row * 64u + (((c ^ ((row >> 1) & 3u)) & 3u) << 4);
}

// ---------------- bf16 split GEMM, 128x256 tile, 512 threads -------------------
// C[m,n] = sum_k A[m,k]*BT[n,k]; planes row-major k-contiguous (ld=1024).
// BK=32, 3 stages, 16 warps (2m x 8n), warp tile 64x32.
#define BK 32
#define APL 8192                  // A plane: 128 rows * 64 B
#define BPL 16384                 // B plane: 256 rows * 64 B
#define OFF_AL  APL
#define OFF_BH  (2 * APL)
#define OFF_BL  (2 * APL + BPL)
#define STAGE_B (2 * APL + 2 * BPL)   // 49152
#define NSTAGE  3
#define SMB     (NSTAGE * STAGE_B)    // 147456

__global__ __launch_bounds__(512, 1)
void mma_gemm(const bf16* __restrict__ gAh, const bf16* __restrict__ gAl, size_t aZ,
              const bf16* __restrict__ gBh, const bf16* __restrict__ gBl,
              float* Cf0, float* Cf1, bf16* Ch, bf16* Cl)
{
    extern __shared__ __align__(16) char smc[];
    const int z = blockIdx.z;
    const bf16* Ah = gAh + (size_t)z * aZ;
    const bf16* Al = gAl + (size_t)z * aZ;
    const bf16* Bh = gBh + (size_t)z * Dd * Dd;
    const bf16* Bl = gBl + (size_t)z * Dd * Dd;
    float* Cf = z ? Cf1 : Cf0;

    const int bm = blockIdx.y * 128;
    const int bn = blockIdx.x * 256;
    const int tid = threadIdx.x;
    const int wid = tid >> 5;
    const int lid = tid & 31;
    const int g = lid >> 2;
    const int t = lid & 3;
    const int wm = (wid >> 3) * 64;       // 2 m-groups
    const int wn = (wid & 7) * 32;        // 8 n-groups

    const uint32_t sbase = smem_u32(smc);

    // cp.async geometry
    const uint32_t rA = (uint32_t)tid >> 2;     // 0..127
    const uint32_t cC = (uint32_t)tid & 3;
    const uint32_t rB1 = rA + 128;              // 128..255
    const uint32_t swA  = swz(rA, cC);
    const uint32_t swB0 = swz(rA, cC);
    const uint32_t swB1 = swz(rB1, cC);
    const bf16* gah = Ah + (size_t)(bm + rA) * 1024 + cC * 8;
    const bf16* gal = Al + (size_t)(bm + rA) * 1024 + cC * 8;
    const bf16* gbh0 = Bh + (size_t)(bn + rA) * 1024 + cC * 8;
    const bf16* gbh1 = Bh + (size_t)(bn + rB1) * 1024 + cC * 8;
    const bf16* gbl0 = Bl + (size_t)(bn + rA) * 1024 + cC * 8;
    const bf16* gbl1 = Bl + (size_t)(bn + rB1) * 1024 + cC * 8;

    auto issue = [&](int k0, int st) {
        uint32_t sb2 = sbase + (uint32_t)st * STAGE_B;
        CPA(sb2 + swA,           gah + k0);
        CPA(sb2 + OFF_AL + swA,  gal + k0);
        CPA(sb2 + OFF_BH + swB0, gbh0 + k0);
        CPA(sb2 + OFF_BH + swB1, gbh1 + k0);
        CPA(sb2 + OFF_BL + swB0, gbl0 + k0);
        CPA(sb2 + OFF_BL + swB1, gbl1 + k0);
    };

    float acc[4][4][4];
    #pragma unroll
    for (int i = 0; i < 4; i++)
        #pragma unroll
        for (int j = 0; j < 4; j++)
            #pragma unroll
            for (int e = 0; e < 4; e++) acc[i][j][e] = 0.0f;

    uint32_t arow[4], brow[2];
    #pragma unroll
    for (int i = 0; i < 4; i++) arow[i] = (uint32_t)(wm + i * 16 + (lid & 15));
    #pragma unroll
    for (int jp = 0; jp < 2; jp++)
        brow[jp] = (uint32_t)(wn + jp * 16 + (lid & 7) + ((lid >> 4) << 3));
    const uint32_t aco = (uint32_t)(lid >> 4);
    const uint32_t bco = (uint32_t)((lid >> 3) & 1);

    auto compute = [&](int buf) {
        const uint32_t bb = sbase + (uint32_t)buf * STAGE_B;
        #pragma unroll
        for (int ks2 = 0; ks2 < 2; ks2++) {
            uint32_t ah[4][4], al[4][4], bh[4][2], bl[4][2];
            #pragma unroll
            for (int i = 0; i < 4; i++) {
                uint32_t off = swz(arow[i], ks2 * 2 + aco);
                LDM4(ah[i], bb + off);
                LDM4(al[i], bb + OFF_AL + off);
            }
            #pragma unroll
            for (int jp = 0; jp < 2; jp++) {
                uint32_t off = swz(brow[jp], ks2 * 2 + bco);
                uint32_t r[4];
                LDM4(r, bb + OFF_BH + off);
                bh[2 * jp][0] = r[0]; bh[2 * jp][1] = r[1];
                bh[2 * jp + 1][0] = r[2]; bh[2 * jp + 1][1] = r[3];
                LDM4(r, bb + OFF_BL + off);
                bl[2 * jp][0] = r[0]; bl[2 * jp][1] = r[1];
                bl[2 * jp + 1][0] = r[2]; bl[2 * jp + 1][1] = r[3];
            }
            #pragma unroll
            for (int i = 0; i < 4; i++)
                #pragma unroll
                for (int j = 0; j < 4; j++) mma16(acc[i][j], ah[i], bl[j]);
            #pragma unroll
            for (int i = 0; i < 4; i++)
                #pragma unroll
                for (int j = 0; j < 4; j++) mma16(acc[i][j], al[i], bh[j]);
            #pragma unroll
            for (int i = 0; i < 4; i++)
                #pragma unroll
                for (int j = 0; j < 4; j++) mma16(acc[i][j], ah[i], bh[j]);
        }
    };

    const int NS = 1024 / BK;   // 32

    issue(0, 0); CPC();
    issue(BK, 1); CPC();

    #pragma unroll 1
    for (int s = 0; s < NS; s++) {
        if (s < NS - 1) { CPW(1); } else { CPW(0); }
        __syncthreads();
        compute(s % 3);
        if (s + 2 < NS) { issue((s + 2) * BK, (s + 2) % 3); CPC(); }
    }

    // epilogue
    if (Cf) {
        #pragma unroll
        for (int i = 0; i < 4; i++) {
            int row = bm + wm + i * 16 + g;
            #pragma unroll
            for (int j = 0; j < 4; j++) {
                int col = bn + wn + j * 8 + 2 * t;
                *(float2*)(Cf + (size_t)row * 1024 + col) =
                    make_float2(acc[i][j][0], acc[i][j][1]);
                *(float2*)(Cf + (size_t)(row + 8) * 1024 + col) =
                    make_float2(acc[i][j][2], acc[i][j][3]);
            }
        }
    } else {
        #pragma unroll
        for (int i = 0; i < 4; i++) {
            int row = bm + wm + i * 16 + g;
            #pragma unroll
            for (int j = 0; j < 4; j++) {
                int col = bn + wn + j * 8 + 2 * t;
                #pragma unroll
                for (int e = 0; e < 2; e++) {
                    float v0 = acc[i][j][2 * e], v1 = acc[i][j][2 * e + 1];
                    bf16 h0 = __float2bfloat16_rn(v0);
                    bf16 h1 = __float2bfloat16_rn(v1);
                    bf16 l0 = __float2bfloat16_rn(v0 - __bfloat162float(h0));
                    bf16 l1 = __float2bfloat16_rn(v1 - __bfloat162float(h1));
                    size_t o = (size_t)(row + 8 * e) * 1024 + col;
                    __nv_bfloat162 hv; hv.x = h0; hv.y = h1;
                    __nv_bfloat162 lv; lv.x = l0; lv.y = l1;
                    *(__nv_bfloat162*)(Ch + o) = hv;
                    *(__nv_bfloat162*)(Cl + o) = lv;
                }
            }
        }
    }
}

// ---------------- split fp32 -> bf16 hi/lo planes ------------------------------
__global__ __launch_bounds__(256)
void split_f32(const float* __restrict__ src, bf16* __restrict__ h, bf16* __restrict__ l)
{
    size_t i = ((size_t)blockIdx.x * 256 + threadIdx.x) * 4;
    float4 v = *(const float4*)(src + i);
    bf16 h0 = __float2bfloat16_rn(v.x), h1 = __float2bfloat16_rn(v.y);
    bf16 h2 = __float2bfloat16_rn(v.z), h3 = __float2bfloat16_rn(v.w);
    bf16 l0 = __float2bfloat16_rn(v.x - __bfloat162float(h0));
    bf16 l1 = __float2bfloat16_rn(v.y - __bfloat162float(h1));
    bf16 l2 = __float2bfloat16_rn(v.z - __bfloat162float(h2));
    bf16 l3 = __float2bfloat16_rn(v.w - __bfloat162float(h3));
    __nv_bfloat162 a, b;
    a.x = h0; a.y = h1; b.x = h2; b.y = h3;
    *(__nv_bfloat162*)(h + i) = a; *(__nv_bfloat162*)(h + i + 2) = b;
    a.x = l0; a.y = l1; b.x = l2; b.y = l3;
    *(__nv_bfloat162*)(l + i) = a; *(__nv_bfloat162*)(l + i + 2) = b;
}

// ---------------- weight transpose + split ------------------------------------
__global__ __launch_bounds__(256)
void transpose_w(const float* __restrict__ Wqk, const float* __restrict__ Wv,
                 bf16* __restrict__ WTh, bf16* __restrict__ WTl)
{
    __shared__ float tbuf[32][33];
    const float* S = blockIdx.z ? Wv : Wqk;
    bf16* Dh = WTh + (size_t)blockIdx.z * Dd * Dd;
    bf16* Dl = WTl + (size_t)blockIdx.z * Dd * Dd;
    int bx = blockIdx.x * 32, by = blockIdx.y * 32;
    int tx = threadIdx.x & 31, ty = threadIdx.x >> 5;
    #pragma unroll
    for (int i = 0; i < 4; i++) {
        int r = ty + i * 8;
        tbuf[r][tx] = S[(size_t)(by + r) * Dd + bx + tx];
    }
    __syncthreads();
    #pragma unroll
    for (int i = 0; i < 4; i++) {
        int r = ty + i * 8;
        float v = tbuf[tx][r];
        bf16 h = __float2bfloat16_rn(v);
        bf16 l = __float2bfloat16_rn(v - __bfloat162float(h));
        size_t o = (size_t)(bx + r) * Dd + by + tx;
        Dh[o] = h; Dl[o] = l;
    }
}

// ---------------- Gram partials (fp32) -----------------------------------------
__global__ __launch_bounds__(256)
void gram_partial(const float* __restrict__ QK, float* __restrict__ Gpart)
{
    const int bh = blockIdx.x;
    const int sp = blockIdx.y;
    const int b = bh >> 4;
    const int h = bh & 15;
    const float* A = QK + (size_t)b * Nt * Dd + h * DH;

    __shared__ float As[32][64];
    const int tid = threadIdx.x;
    const int tx = tid & 15, ty = tid >> 4;

    float acc[4][4];
    #pragma unroll
    for (int i = 0; i < 4; i++)
        #pragma unroll
        for (int j = 0; j < 4; j++) acc[i][j] = 0.0f;

    const int n0base = sp * (Nt / NSPLIT);
    for (int n0 = n0base; n0 < n0base + Nt / NSPLIT; n0 += 32) {
        #pragma unroll
        for (int i = 0; i < 2; i++) {
            int idx = tid + i * 256;
            int r = idx >> 4;
            int c4 = (idx & 15) * 4;
            *(float4*)&As[r][c4] = *(const float4*)(A + (size_t)(n0 + r) * Dd + c4);
        }
        __syncthreads();
        #pragma unroll
        for (int kk = 0; kk < 32; kk++) {
            float rc[4], rd[4];
            #pragma unroll
            for (int i = 0; i < 4; i++) rc[i] = As[kk][ty * 4 + i];
            #pragma unroll
            for (int j = 0; j < 4; j++) rd[j] = As[kk][tx * 4 + j];
            #pragma unroll
            for (int i = 0; i < 4; i++)
                #pragma unroll
                for (int j = 0; j < 4; j++)
                    acc[i][j] += rc[i] * rd[j];
        }
        __syncthreads();
    }

    float* gp = Gpart + ((size_t)bh * NSPLIT + sp) * (DH * DH);
    #pragma unroll
    for (int i = 0; i < 4; i++)
        #pragma unroll
        for (int j = 0; j < 4; j++)
            gp[(ty * 4 + i) * DH + tx * 4 + j] = acc[i][j];
}

// ---------------- reduce + softmax ----------------------------------------------
__global__ __launch_bounds__(256)
void softmax_kernel(const float* __restrict__ Gpart,
                    const float* __restrict__ tau,
                    float* __restrict__ attn)
{
    const int bh = blockIdx.x;
    const int h = bh & 15;
    __shared__ float G[DH * DH];
    const int tid = threadIdx.x;

    const float* base = Gpart + (size_t)bh * NSPLIT * (DH * DH);
    for (int e = tid; e < DH * DH; e += 256) {
        float s = 0.0f;
        #pragma unroll
        for (int p = 0; p < NSPLIT; p++) s += base[(size_t)p * (DH * DH) + e];
        G[e] = s;
    }
    __syncthreads();

    if (tid < DH) {
        const int c = tid;
        const float tauh = tau[h];
        const float scale = 0.011048543456039806f;
        const float qc = G[c * DH + c];
        float l[DH];
        float mx = -1e30f;
        #pragma unroll 8
        for (int d = 0; d < DH; d++) {
            float v = (2.0f * G[c * DH + d] - qc - G[d * DH + d]) * scale * tauh;
            l[d] = v;
            mx = fmaxf(mx, v);
        }
        float sum = 0.0f;
        #pragma unroll 8
        for (int d = 0; d < DH; d++) { float e = __expf(l[d] - mx); l[d] = e; sum += e; }
        const float inv = 1.0f / sum;
        float* ap = attn + (size_t)bh * (DH * DH) + c * DH;
        #pragma unroll 8
        for (int d = 0; d < DH; d++) ap[d] = l[d] * inv;
    }
}

// ---------------- fold attn into W_out, emit split M^T ---------------------------
__global__ __launch_bounds__(256)
void build_mT(const float* __restrict__ attn,
              const float* __restrict__ Wout,
              bf16* __restrict__ MTh, bf16* __restrict__ MTl)
{
    const int bh = blockIdx.y;
    const int b = bh >> 4, h = bh & 15;
    const int j0 = blockIdx.x * 128;

    __shared__ float Asm[DH * DH];
    __shared__ float Ws[DH][128];

    const int tid = threadIdx.x;
    const float* ap = attn + (size_t)bh * (DH * DH);
    for (int e = tid; e < DH * DH; e += 256) Asm[e] = ap[e];

    #pragma unroll
    for (int i = 0; i < 8; i++) {
        int idx = tid + i * 256;
        int r = idx >> 5;
        int c4 = (idx & 31) * 4;
        *(float4*)&Ws[r][c4] =
            *(const float4*)(Wout + (size_t)(h * DH + r) * Dd + j0 + c4);
    }
    __syncthreads();

    const int tx = tid & 15, ty = tid >> 4;
    float acc[8][4];
    #pragma unroll
    for (int i = 0; i < 8; i++)
        #pragma unroll
        for (int j = 0; j < 4; j++) acc[i][j] = 0.0f;

    for (int c = 0; c < DH; c++) {
        float4 av = *(float4*)&Asm[c * DH + tx * 4];
        #pragma unroll
        for (int i = 0; i < 8; i++) {
            float w = Ws[c][ty * 8 + i];
            acc[i][0] += w * av.x;
            acc[i][1] += w * av.y;
            acc[i][2] += w * av.z;
            acc[i][3] += w * av.w;
        }
    }

    bf16* Mh = MTh + (size_t)b * Dd * Dd;
    bf16* Ml = MTl + (size_t)b * Dd * Dd;
    #pragma unroll
    for (int i = 0; i < 8; i++) {
        int j = j0 + ty * 8 + i;
        size_t o = (size_t)j * Dd + h * DH + tx * 4;
        #pragma unroll
        for (int e = 0; e < 4; e++) {
            float v = acc[i][e];
            bf16 hh = __float2bfloat16_rn(v);
            bf16 ll = __float2bfloat16_rn(v - __bfloat162float(hh));
            Mh[o + e] = hh; Ml[o + e] = ll;
        }
    }
}

// ----------------------------------------------------------------------------------
extern "C" void kernel_launch(void* const* d_in, const int* in_sizes, int n_in,
                              void* d_out, int out_size)
{
    const float* x    = (const float*)d_in[0];
    const float* Wqk  = (const float*)d_in[1];
    const float* Wv   = (const float*)d_in[2];
    const float* Wout = (const float*)d_in[3];
    const float* tau  = (const float*)d_in[4];
    float* out = (float*)d_out;

    void *pqk, *pxh, *pxl, *pvh, *pvl, *pwth, *pwtl, *pmth, *pmtl, *pg, *pa;
    cudaGetSymbolAddress(&pqk, g_qk);
    cudaGetSymbolAddress(&pxh, g_xh);
    cudaGetSymbolAddress(&pxl, g_xl);
    cudaGetSymbolAddress(&pvh, g_vh);
    cudaGetSymbolAddress(&pvl, g_vl);
    cudaGetSymbolAddress(&pwth, g_wth);
    cudaGetSymbolAddress(&pwtl, g_wtl);
    cudaGetSymbolAddress(&pmth, g_mth);
    cudaGetSymbolAddress(&pmtl, g_mtl);
    cudaGetSymbolAddress(&pg, g_gpart);
    cudaGetSymbolAddress(&pa, g_attn);

    float* QK = (float*)pqk;
    bf16 *Xh = (bf16*)pxh, *Xl = (bf16*)pxl;
    bf16 *Vh = (bf16*)pvh, *Vl = (bf16*)pvl;
    bf16 *WTh = (bf16*)pwth, *WTl = (bf16*)pwtl;
    bf16 *MTh = (bf16*)pmth, *MTl = (bf16*)pmtl;
    float* Gp = (float*)pg;
    float* At = (float*)pa;

    cudaFuncSetAttribute(mma_gemm, cudaFuncAttributeMaxDynamicSharedMemorySize, SMB);

    // 0a: split X into bf16 hi/lo planes
    split_f32<<<(size_t)Mrows * Dd / 1024, 256>>>(x, Xh, Xl);
    // 0b: transpose + split weights (n-major)
    transpose_w<<<dim3(32, 32, 2), 256>>>(Wqk, Wv, WTh, WTl);
    // 1: projections; z=0 -> QK (fp32), z=1 -> V (split bf16 planes)
    mma_gemm<<<dim3(4, 128, 2), 512, SMB>>>(Xh, Xl, 0,
                                            WTh, WTl,
                                            QK, nullptr, Vh, Vl);
    // 2: Gram partials (fp32)
    gram_partial<<<dim3(32, NSPLIT), 256>>>(QK, Gp);
    // 3: reduce + softmax
    softmax_kernel<<<32, 256>>>(Gp, tau, At);
    // 4: fold attn into W_out (transposed, split)
    build_mT<<<dim3(8, 32), 256>>>(At, Wout, MTh, MTl);
    // 5: out_b = V_b @ M_b
    mma_gemm<<<dim3(4, 64, 2), 512, SMB>>>(Vh, Vl, (size_t)Nt * Dd,
                                           MTh, MTl,
                                           out, out + (size_t)Nt * Dd, nullptr, nullptr);
}

// round 7
// speedup vs baseline: 3.1537x; 1.1809x over previous
#include <cuda_runtime.h>
#include <cuda_bf16.h>
#include <cstdint>
#include <cstddef>

typedef __nv_bfloat16 bf16;

// Problem constants
#define Bq   2
#define Nt   8192
#define Dd   1024
#define Hh   16
#define DH   64
#define Mrows (Bq * Nt)
#define NSPLIT 16

// ---------------- scratch ---------------------------------------------------
__device__ float g_qk[(size_t)Mrows * Dd];                 // 64 MB
__device__ bf16  g_xh[(size_t)Mrows * Dd];                 // 32 MB
__device__ bf16  g_xl[(size_t)Mrows * Dd];
__device__ bf16  g_wth[(size_t)Dd * Dd];                   // WqkT hi
__device__ bf16  g_wtl[(size_t)Dd * Dd];
__device__ bf16  g_wvh[(size_t)Dd * Dd];                   // Wv (row-major) hi
__device__ bf16  g_wvl[(size_t)Dd * Dd];
__device__ bf16  g_mth[(size_t)Bq * Dd * Dd];              // MT per batch
__device__ bf16  g_mtl[(size_t)Bq * Dd * Dd];
__device__ bf16  g_nth[(size_t)Bq * Dd * Dd];              // NT per batch
__device__ bf16  g_ntl[(size_t)Bq * Dd * Dd];
__device__ float g_gpart[(size_t)Bq * Hh * NSPLIT * DH * DH];
__device__ float g_attn [(size_t)Bq * Hh * DH * DH];

// ---------------- PTX helpers -------------------------------------------------
__device__ __forceinline__ uint32_t smem_u32(const void* p) {
    uint32_t a;
    asm("{ .reg .u64 t; cvta.to.shared.u64 t, %1; cvt.u32.u64 %0, t; }"
        : "=r"(a) : "l"(p));
    return a;
}

#define LDM4(r, addr)                                                          \
    asm volatile("ldmatrix.sync.aligned.m8n8.x4.shared.b16 {%0,%1,%2,%3}, [%4];" \
        : "=r"((r)[0]), "=r"((r)[1]), "=r"((r)[2]), "=r"((r)[3]) : "r"(addr))

__device__ __forceinline__ void mma16(float* c, const uint32_t* a, const uint32_t* b) {
    asm volatile(
        "mma.sync.aligned.m16n8k16.row.col.f32.bf16.bf16.f32 "
        "{%0,%1,%2,%3}, {%4,%5,%6,%7}, {%8,%9}, {%0,%1,%2,%3};"
        : "+f"(c[0]), "+f"(c[1]), "+f"(c[2]), "+f"(c[3])
        : "r"(a[0]), "r"(a[1]), "r"(a[2]), "r"(a[3]), "r"(b[0]), "r"(b[1]));
}

#define CPA(dst, src) \
    asm volatile("cp.async.cg.shared.global [%0], [%1], 16;" :: "r"(dst), "l"(src) : "memory")
#define CPC() asm volatile("cp.async.commit_group;" ::: "memory")
#define CPW(n) asm volatile("cp.async.wait_group %0;" :: "n"(n) : "memory")

__device__ __forceinline__ uint32_t swz(uint32_t row, uint32_t c) {
    return row * 64u + (((c ^ ((row >> 1) & 3u)) & 3u) << 4);
}

// ---------------- bf16 split GEMM, 128x256 tile, 512 threads -------------------
// C[m,n] = sum_k A[m,k]*BT[n,k]; planes row-major k-contiguous (ld=1024).
#define BK 32
#define APL 8192
#define BPL 16384
#define OFF_AL  APL
#define OFF_BH  (2 * APL)
#define OFF_BL  (2 * APL + BPL)
#define STAGE_B (2 * APL + 2 * BPL)
#define NSTAGE  3
#define SMB     (NSTAGE * STAGE_B)    // 147456

__global__ __launch_bounds__(512, 1)
void mma_gemm(const bf16* __restrict__ gAh, const bf16* __restrict__ gAl, size_t aZ,
              const bf16* __restrict__ gBh, const bf16* __restrict__ gBl, size_t bZ,
              float* Cf0, float* Cf1, bf16* Ch, bf16* Cl, size_t cZ)
{
    extern __shared__ __align__(16) char smc[];
    const int z = blockIdx.z;
    const bf16* Ah = gAh + (size_t)z * aZ;
    const bf16* Al = gAl + (size_t)z * aZ;
    const bf16* Bh = gBh + (size_t)z * bZ;
    const bf16* Bl = gBl + (size_t)z * bZ;
    float* Cf = z ? Cf1 : Cf0;

    const int bm = blockIdx.y * 128;
    const int bn = blockIdx.x * 256;
    const int tid = threadIdx.x;
    const int wid = tid >> 5;
    const int lid = tid & 31;
    const int g = lid >> 2;
    const int t = lid & 3;
    const int wm = (wid >> 3) * 64;
    const int wn = (wid & 7) * 32;

    const uint32_t sbase = smem_u32(smc);

    const uint32_t rA = (uint32_t)tid >> 2;
    const uint32_t cC = (uint32_t)tid & 3;
    const uint32_t rB1 = rA + 128;
    const uint32_t swA  = swz(rA, cC);
    const uint32_t swB0 = swz(rA, cC);
    const uint32_t swB1 = swz(rB1, cC);
    const bf16* gah = Ah + (size_t)(bm + rA) * 1024 + cC * 8;
    const bf16* gal = Al + (size_t)(bm + rA) * 1024 + cC * 8;
    const bf16* gbh0 = Bh + (size_t)(bn + rA) * 1024 + cC * 8;
    const bf16* gbh1 = Bh + (size_t)(bn + rB1) * 1024 + cC * 8;
    const bf16* gbl0 = Bl + (size_t)(bn + rA) * 1024 + cC * 8;
    const bf16* gbl1 = Bl + (size_t)(bn + rB1) * 1024 + cC * 8;

    auto issue = [&](int k0, int st) {
        uint32_t sb2 = sbase + (uint32_t)st * STAGE_B;
        CPA(sb2 + swA,           gah + k0);
        CPA(sb2 + OFF_AL + swA,  gal + k0);
        CPA(sb2 + OFF_BH + swB0, gbh0 + k0);
        CPA(sb2 + OFF_BH + swB1, gbh1 + k0);
        CPA(sb2 + OFF_BL + swB0, gbl0 + k0);
        CPA(sb2 + OFF_BL + swB1, gbl1 + k0);
    };

    float acc[4][4][4];
    #pragma unroll
    for (int i = 0; i < 4; i++)
        #pragma unroll
        for (int j = 0; j < 4; j++)
            #pragma unroll
            for (int e = 0; e < 4; e++) acc[i][j][e] = 0.0f;

    uint32_t arow[4], brow[2];
    #pragma unroll
    for (int i = 0; i < 4; i++) arow[i] = (uint32_t)(wm + i * 16 + (lid & 15));
    #pragma unroll
    for (int jp = 0; jp < 2; jp++)
        brow[jp] = (uint32_t)(wn + jp * 16 + (lid & 7) + ((lid >> 4) << 3));
    const uint32_t aco = (uint32_t)(lid >> 4);
    const uint32_t bco = (uint32_t)((lid >> 3) & 1);

    auto compute = [&](int buf) {
        const uint32_t bb = sbase + (uint32_t)buf * STAGE_B;
        #pragma unroll
        for (int ks2 = 0; ks2 < 2; ks2++) {
            uint32_t ah[4][4], al[4][4], bh[4][2], bl[4][2];
            #pragma unroll
            for (int i = 0; i < 4; i++) {
                uint32_t off = swz(arow[i], ks2 * 2 + aco);
                LDM4(ah[i], bb + off);
                LDM4(al[i], bb + OFF_AL + off);
            }
            #pragma unroll
            for (int jp = 0; jp < 2; jp++) {
                uint32_t off = swz(brow[jp], ks2 * 2 + bco);
                uint32_t r[4];
                LDM4(r, bb + OFF_BH + off);
                bh[2 * jp][0] = r[0]; bh[2 * jp][1] = r[1];
                bh[2 * jp + 1][0] = r[2]; bh[2 * jp + 1][1] = r[3];
                LDM4(r, bb + OFF_BL + off);
                bl[2 * jp][0] = r[0]; bl[2 * jp][1] = r[1];
                bl[2 * jp + 1][0] = r[2]; bl[2 * jp + 1][1] = r[3];
            }
            #pragma unroll
            for (int i = 0; i < 4; i++)
                #pragma unroll
                for (int j = 0; j < 4; j++) mma16(acc[i][j], ah[i], bl[j]);
            #pragma unroll
            for (int i = 0; i < 4; i++)
                #pragma unroll
                for (int j = 0; j < 4; j++) mma16(acc[i][j], al[i], bh[j]);
            #pragma unroll
            for (int i = 0; i < 4; i++)
                #pragma unroll
                for (int j = 0; j < 4; j++) mma16(acc[i][j], ah[i], bh[j]);
        }
    };

    const int NS = 1024 / BK;

    issue(0, 0); CPC();
    issue(BK, 1); CPC();

    #pragma unroll 1
    for (int s = 0; s < NS; s++) {
        if (s < NS - 1) { CPW(1); } else { CPW(0); }
        __syncthreads();
        compute(s % 3);
        if (s + 2 < NS) { issue((s + 2) * BK, (s + 2) % 3); CPC(); }
    }

    // epilogue
    if (Cf) {
        #pragma unroll
        for (int i = 0; i < 4; i++) {
            int row = bm + wm + i * 16 + g;
            #pragma unroll
            for (int j = 0; j < 4; j++) {
                int col = bn + wn + j * 8 + 2 * t;
                *(float2*)(Cf + (size_t)row * 1024 + col) =
                    make_float2(acc[i][j][0], acc[i][j][1]);
                *(float2*)(Cf + (size_t)(row + 8) * 1024 + col) =
                    make_float2(acc[i][j][2], acc[i][j][3]);
            }
        }
    } else {
        bf16* Chz = Ch + (size_t)z * cZ;
        bf16* Clz = Cl + (size_t)z * cZ;
        #pragma unroll
        for (int i = 0; i < 4; i++) {
            int row = bm + wm + i * 16 + g;
            #pragma unroll
            for (int j = 0; j < 4; j++) {
                int col = bn + wn + j * 8 + 2 * t;
                #pragma unroll
                for (int e = 0; e < 2; e++) {
                    float v0 = acc[i][j][2 * e], v1 = acc[i][j][2 * e + 1];
                    bf16 h0 = __float2bfloat16_rn(v0);
                    bf16 h1 = __float2bfloat16_rn(v1);
                    bf16 l0 = __float2bfloat16_rn(v0 - __bfloat162float(h0));
                    bf16 l1 = __float2bfloat16_rn(v1 - __bfloat162float(h1));
                    size_t o = (size_t)(row + 8 * e) * 1024 + col;
                    __nv_bfloat162 hv; hv.x = h0; hv.y = h1;
                    __nv_bfloat162 lv; lv.x = l0; lv.y = l1;
                    *(__nv_bfloat162*)(Chz + o) = hv;
                    *(__nv_bfloat162*)(Clz + o) = lv;
                }
            }
        }
    }
}

// ---------------- split fp32 -> bf16 hi/lo planes ------------------------------
__global__ __launch_bounds__(256)
void split_f32(const float* __restrict__ src, bf16* __restrict__ h, bf16* __restrict__ l)
{
    size_t i = ((size_t)blockIdx.x * 256 + threadIdx.x) * 4;
    float4 v = *(const float4*)(src + i);
    bf16 h0 = __float2bfloat16_rn(v.x), h1 = __float2bfloat16_rn(v.y);
    bf16 h2 = __float2bfloat16_rn(v.z), h3 = __float2bfloat16_rn(v.w);
    bf16 l0 = __float2bfloat16_rn(v.x - __bfloat162float(h0));
    bf16 l1 = __float2bfloat16_rn(v.y - __bfloat162float(h1));
    bf16 l2 = __float2bfloat16_rn(v.z - __bfloat162float(h2));
    bf16 l3 = __float2bfloat16_rn(v.w - __bfloat162float(h3));
    __nv_bfloat162 a, b;
    a.x = h0; a.y = h1; b.x = h2; b.y = h3;
    *(__nv_bfloat162*)(h + i) = a; *(__nv_bfloat162*)(h + i + 2) = b;
    a.x = l0; a.y = l1; b.x = l2; b.y = l3;
    *(__nv_bfloat162*)(l + i) = a; *(__nv_bfloat162*)(l + i + 2) = b;
}

// ---------------- Wqk transpose + split ----------------------------------------
__global__ __launch_bounds__(256)
void transpose_w(const float* __restrict__ W, bf16* __restrict__ WTh, bf16* __restrict__ WTl)
{
    __shared__ float tbuf[32][33];
    int bx = blockIdx.x * 32, by = blockIdx.y * 32;
    int tx = threadIdx.x & 31, ty = threadIdx.x >> 5;
    #pragma unroll
    for (int i = 0; i < 4; i++) {
        int r = ty + i * 8;
        tbuf[r][tx] = W[(size_t)(by + r) * Dd + bx + tx];
    }
    __syncthreads();
    #pragma unroll
    for (int i = 0; i < 4; i++) {
        int r = ty + i * 8;
        float v = tbuf[tx][r];
        bf16 h = __float2bfloat16_rn(v);
        bf16 l = __float2bfloat16_rn(v - __bfloat162float(h));
        size_t o = (size_t)(bx + r) * Dd + by + tx;
        WTh[o] = h; WTl[o] = l;
    }
}

// ---------------- Gram partials (fp32) -----------------------------------------
__global__ __launch_bounds__(256)
void gram_partial(const float* __restrict__ QK, float* __restrict__ Gpart)
{
    const int bh = blockIdx.x;
    const int sp = blockIdx.y;
    const int b = bh >> 4;
    const int h = bh & 15;
    const float* A = QK + (size_t)b * Nt * Dd + h * DH;

    __shared__ float As[32][64];
    const int tid = threadIdx.x;
    const int tx = tid & 15, ty = tid >> 4;

    float acc[4][4];
    #pragma unroll
    for (int i = 0; i < 4; i++)
        #pragma unroll
        for (int j = 0; j < 4; j++) acc[i][j] = 0.0f;

    const int n0base = sp * (Nt / NSPLIT);
    for (int n0 = n0base; n0 < n0base + Nt / NSPLIT; n0 += 32) {
        #pragma unroll
        for (int i = 0; i < 2; i++) {
            int idx = tid + i * 256;
            int r = idx >> 4;
            int c4 = (idx & 15) * 4;
            *(float4*)&As[r][c4] = *(const float4*)(A + (size_t)(n0 + r) * Dd + c4);
        }
        __syncthreads();
        #pragma unroll
        for (int kk = 0; kk < 32; kk++) {
            float rc[4], rd[4];
            #pragma unroll
            for (int i = 0; i < 4; i++) rc[i] = As[kk][ty * 4 + i];
            #pragma unroll
            for (int j = 0; j < 4; j++) rd[j] = As[kk][tx * 4 + j];
            #pragma unroll
            for (int i = 0; i < 4; i++)
                #pragma unroll
                for (int j = 0; j < 4; j++)
                    acc[i][j] += rc[i] * rd[j];
        }
        __syncthreads();
    }

    float* gp = Gpart + ((size_t)bh * NSPLIT + sp) * (DH * DH);
    #pragma unroll
    for (int i = 0; i < 4; i++)
        #pragma unroll
        for (int j = 0; j < 4; j++)
            gp[(ty * 4 + i) * DH + tx * 4 + j] = acc[i][j];
}

// ---------------- reduce + softmax ----------------------------------------------
__global__ __launch_bounds__(256)
void softmax_kernel(const float* __restrict__ Gpart,
                    const float* __restrict__ tau,
                    float* __restrict__ attn)
{
    const int bh = blockIdx.x;
    const int h = bh & 15;
    __shared__ float G[DH * DH];
    const int tid = threadIdx.x;

    const float* base = Gpart + (size_t)bh * NSPLIT * (DH * DH);
    for (int e = tid; e < DH * DH; e += 256) {
        float s = 0.0f;
        #pragma unroll
        for (int p = 0; p < NSPLIT; p++) s += base[(size_t)p * (DH * DH) + e];
        G[e] = s;
    }
    __syncthreads();

    if (tid < DH) {
        const int c = tid;
        const float tauh = tau[h];
        const float scale = 0.011048543456039806f;
        const float qc = G[c * DH + c];
        float l[DH];
        float mx = -1e30f;
        #pragma unroll 8
        for (int d = 0; d < DH; d++) {
            float v = (2.0f * G[c * DH + d] - qc - G[d * DH + d]) * scale * tauh;
            l[d] = v;
            mx = fmaxf(mx, v);
        }
        float sum = 0.0f;
        #pragma unroll 8
        for (int d = 0; d < DH; d++) { float e = __expf(l[d] - mx); l[d] = e; sum += e; }
        const float inv = 1.0f / sum;
        float* ap = attn + (size_t)bh * (DH * DH) + c * DH;
        #pragma unroll 8
        for (int d = 0; d < DH; d++) ap[d] = l[d] * inv;
    }
}

// ---------------- fold attn into W_out, emit split M^T ---------------------------
// MT_b[j, h*64+d] = sum_c attn[bh][c,d] * Wout[h*64+c, j]
__global__ __launch_bounds__(256)
void build_mT(const float* __restrict__ attn,
              const float* __restrict__ Wout,
              bf16* __restrict__ MTh, bf16* __restrict__ MTl)
{
    const int bh = blockIdx.y;
    const int b = bh >> 4, h = bh & 15;
    const int j0 = blockIdx.x * 128;

    __shared__ float Asm[DH * DH];
    __shared__ float Ws[DH][128];

    const int tid = threadIdx.x;
    const float* ap = attn + (size_t)bh * (DH * DH);
    for (int e = tid; e < DH * DH; e += 256) Asm[e] = ap[e];

    #pragma unroll
    for (int i = 0; i < 8; i++) {
        int idx = tid + i * 256;
        int r = idx >> 5;
        int c4 = (idx & 31) * 4;
        *(float4*)&Ws[r][c4] =
            *(const float4*)(Wout + (size_t)(h * DH + r) * Dd + j0 + c4);
    }
    __syncthreads();

    const int tx = tid & 15, ty = tid >> 4;
    float acc[8][4];
    #pragma unroll
    for (int i = 0; i < 8; i++)
        #pragma unroll
        for (int j = 0; j < 4; j++) acc[i][j] = 0.0f;

    for (int c = 0; c < DH; c++) {
        float4 av = *(float4*)&Asm[c * DH + tx * 4];
        #pragma unroll
        for (int i = 0; i < 8; i++) {
            float w = Ws[c][ty * 8 + i];
            acc[i][0] += w * av.x;
            acc[i][1] += w * av.y;
            acc[i][2] += w * av.z;
            acc[i][3] += w * av.w;
        }
    }

    bf16* Mh = MTh + (size_t)b * Dd * Dd;
    bf16* Ml = MTl + (size_t)b * Dd * Dd;
    #pragma unroll
    for (int i = 0; i < 8; i++) {
        int j = j0 + ty * 8 + i;
        size_t o = (size_t)j * Dd + h * DH + tx * 4;
        #pragma unroll
        for (int e = 0; e < 4; e++) {
            float v = acc[i][e];
            bf16 hh = __float2bfloat16_rn(v);
            bf16 ll = __float2bfloat16_rn(v - __bfloat162float(hh));
            Mh[o + e] = hh; Ml[o + e] = ll;
        }
    }
}

// ----------------------------------------------------------------------------------
extern "C" void kernel_launch(void* const* d_in, const int* in_sizes, int n_in,
                              void* d_out, int out_size)
{
    const float* x    = (const float*)d_in[0];
    const float* Wqk  = (const float*)d_in[1];
    const float* Wv   = (const float*)d_in[2];
    const float* Wout = (const float*)d_in[3];
    const float* tau  = (const float*)d_in[4];
    float* out = (float*)d_out;

    void *pqk, *pxh, *pxl, *pwth, *pwtl, *pwvh, *pwvl, *pmth, *pmtl, *pnth, *pntl, *pg, *pa;
    cudaGetSymbolAddress(&pqk, g_qk);
    cudaGetSymbolAddress(&pxh, g_xh);
    cudaGetSymbolAddress(&pxl, g_xl);
    cudaGetSymbolAddress(&pwth, g_wth);
    cudaGetSymbolAddress(&pwtl, g_wtl);
    cudaGetSymbolAddress(&pwvh, g_wvh);
    cudaGetSymbolAddress(&pwvl, g_wvl);
    cudaGetSymbolAddress(&pmth, g_mth);
    cudaGetSymbolAddress(&pmtl, g_mtl);
    cudaGetSymbolAddress(&pnth, g_nth);
    cudaGetSymbolAddress(&pntl, g_ntl);
    cudaGetSymbolAddress(&pg, g_gpart);
    cudaGetSymbolAddress(&pa, g_attn);

    float* QK = (float*)pqk;
    bf16 *Xh = (bf16*)pxh, *Xl = (bf16*)pxl;
    bf16 *WTh = (bf16*)pwth, *WTl = (bf16*)pwtl;
    bf16 *WVh = (bf16*)pwvh, *WVl = (bf16*)pwvl;
    bf16 *MTh = (bf16*)pmth, *MTl = (bf16*)pmtl;
    bf16 *NTh = (bf16*)pnth, *NTl = (bf16*)pntl;
    float* Gp = (float*)pg;
    float* At = (float*)pa;

    cudaFuncSetAttribute(mma_gemm, cudaFuncAttributeMaxDynamicSharedMemorySize, SMB);

    // 0a: split X into bf16 hi/lo planes
    split_f32<<<(size_t)Mrows * Dd / 1024, 256>>>(x, Xh, Xl);
    // 0b: split Wv (row-major == n-major operand for NT GEMM)
    split_f32<<<(size_t)Dd * Dd / 1024, 256>>>(Wv, WVh, WVl);
    // 0c: transpose + split Wqk
    transpose_w<<<dim3(32, 32), 256>>>(Wqk, WTh, WTl);
    // 1: QK = X @ Wqk
    mma_gemm<<<dim3(4, 128, 1), 512, SMB>>>(Xh, Xl, 0, WTh, WTl, 0,
                                            QK, QK, nullptr, nullptr, 0);
    // 2: Gram partials
    gram_partial<<<dim3(32, NSPLIT), 256>>>(QK, Gp);
    // 3: reduce + softmax
    softmax_kernel<<<32, 256>>>(Gp, tau, At);
    // 4: fold attn into W_out (transposed, split)
    build_mT<<<dim3(8, 32), 256>>>(At, Wout, MTh, MTl);
    // 5: NT_b = MT_b @ Wv^T  (split bf16 out)
    mma_gemm<<<dim3(4, 8, 2), 512, SMB>>>(MTh, MTl, (size_t)Dd * Dd,
                                          WVh, WVl, 0,
                                          nullptr, nullptr, NTh, NTl, (size_t)Dd * Dd);
    // 6: out_b = X_b @ N_b
    mma_gemm<<<dim3(4, 64, 2), 512, SMB>>>(Xh, Xl, (size_t)Nt * Dd,
                                           NTh, NTl, (size_t)Dd * Dd,
                                           out, out + (size_t)Nt * Dd, nullptr, nullptr, 0);
}